// round 14
// baseline (speedup 1.0000x reference)
#include <cuda_runtime.h>
#include <cuda_bf16.h>
#include <math.h>
#include <stdint.h>

#define BS   256
#define SEQ  201
#define DSSL 1024
#define D1   128
#define D2   64
#define NN   67
#define NP   53
#define NPAIR (NN*NN)      // 4489
#define NU   2278          // upper-triangle pairs (i<=j)
#define NUT  2304
#define EPSBN 1e-5f
#define MTOT  (BS*SEQ)     // 51456
#define NODES (BS*NN)      // 17152 = 134*128

// ---------------- scratch (device globals; no runtime allocation) ----------
__device__ float g_x [NODES * D1];
__device__ float g_y [NODES * D2];         // X @ W_pa
__device__ float g_z [NODES * D2];         // X @ W_pn
__device__ float g_logit[BS * NPAIR];
__device__ uint32_t g_pair[NUT];           // packed (i<<8)|j upper-tri table
__device__ float g_sc1[D1], g_of1[D1];     // folded bias+BN1 scale/offset
// pre-swizzled (SW64, 64B rows) pre-split bf16 weight images
__device__ __align__(16) unsigned char g_Bll_h[32 * 8192];
__device__ __align__(16) unsigned char g_Bll_l[32 * 8192];
__device__ __align__(16) unsigned char g_Bap_h[4 * 4096];   // k-slot-permuted
__device__ __align__(16) unsigned char g_Bap_l[4 * 4096];
__device__ __align__(16) unsigned char g_Byz_h[4 * 8192];   // [W_pa|W_pn]^T
__device__ __align__(16) unsigned char g_Byz_l[4 * 8192];

// ------------------------------ helpers ------------------------------------
__device__ __forceinline__ float selu_f(float v) {
    const float a = 1.6732632423543772f, s = 1.0507009873554805f;
    return v > 0.f ? s * v : s * a * expm1f(v);
}
__device__ __forceinline__ float tanh_f(float x) {
    float e = __expf(2.0f * x);
    return 1.0f - __fdividef(2.0f, e + 1.0f);
}
__host__ __device__ __forceinline__ uint32_t sw64(uint32_t o) {
    return o ^ ((o >> 3) & 0x30);
}
__device__ __forceinline__ uint32_t smem_u32(const void* p) {
    uint32_t a;
    asm("{ .reg .u64 t; cvta.to.shared.u64 t, %1; cvt.u32.u64 %0, t; }"
        : "=r"(a) : "l"(p));
    return a;
}
__device__ __forceinline__ void split2(float v0, float v1, uint32_t& h, uint32_t& l) {
    __nv_bfloat162 hp, lp;
    hp.x = __float2bfloat16(v0);  hp.y = __float2bfloat16(v1);
    lp.x = __float2bfloat16(v0 - __bfloat162float(hp.x));
    lp.y = __float2bfloat16(v1 - __bfloat162float(hp.y));
    h = *reinterpret_cast<uint32_t*>(&hp);
    l = *reinterpret_cast<uint32_t*>(&lp);
}
__device__ __forceinline__ void mma_bf16(float* c,
    uint32_t a0, uint32_t a1, uint32_t a2, uint32_t a3,
    uint32_t b0, uint32_t b1)
{
    asm volatile(
      "mma.sync.aligned.m16n8k16.row.col.f32.bf16.bf16.f32 "
      "{%0,%1,%2,%3},{%4,%5,%6,%7},{%8,%9},{%0,%1,%2,%3};\n"
      : "+f"(c[0]), "+f"(c[1]), "+f"(c[2]), "+f"(c[3])
      : "r"(a0), "r"(a1), "r"(a2), "r"(a3), "r"(b0), "r"(b1));
}
#define LDSM4(r, a) \
    asm volatile("ldmatrix.sync.aligned.m8n8.x4.shared.b16 {%0,%1,%2,%3}, [%4];" \
        : "=r"((r)[0]), "=r"((r)[1]), "=r"((r)[2]), "=r"((r)[3]) : "r"(a))
#define CPA16(d, s) \
    asm volatile("cp.async.ca.shared.global [%0], [%1], 16;" :: "r"(d), "l"(s))
#define CPCOMMIT() asm volatile("cp.async.commit_group;" ::: "memory")
#define CPWAIT()   asm volatile("cp.async.wait_group 0;" ::: "memory")

// ========= K0: weight prep (split+swizzle), pair table, BN1 fold ===========
#define K0_R1 (D1*DSSL)
#define K0_R2 (K0_R1 + D1*D2)
#define K0_R3 (K0_R2 + NUT)
#define K0_R4 (K0_R3 + D1)
#define K0_R5 (K0_R4 + D1*D1)
__global__ void k0(const float* __restrict__ Wll, const float* __restrict__ Wap,
                   const float* __restrict__ bll, const float* __restrict__ g1,
                   const float* __restrict__ b1,  const float* __restrict__ m1,
                   const float* __restrict__ v1,
                   const float* __restrict__ Wpa, const float* __restrict__ Wpn)
{
    int idx = blockIdx.x * 256 + threadIdx.x;
    if (idx < K0_R1) {
        int n = idx >> 10, k = idx & 1023;
        float v = Wll[(size_t)k * D1 + n];
        __nv_bfloat16 h = __float2bfloat16(v);
        __nv_bfloat16 l = __float2bfloat16(v - __bfloat162float(h));
        uint32_t dst = (k >> 5) * 8192 + sw64(n * 64 + (k & 31) * 2);
        *(__nv_bfloat16*)(g_Bll_h + dst) = h;
        *(__nv_bfloat16*)(g_Bll_l + dst) = l;
    } else if (idx < K0_R2) {
        int r = idx - K0_R1;
        int k = r >> 6, c = r & 63;
        float v = Wap[(size_t)k * D2 + c];
        __nv_bfloat16 h = __float2bfloat16(v);
        __nv_bfloat16 l = __float2bfloat16(v - __bfloat162float(h));
        int kk = k & 15;
        int s = 2 * (kk >> 2) + (kk & 1) + 8 * ((kk >> 1) & 1);
        uint32_t col = (uint32_t)(((k >> 4) & 1) * 16 + s);
        uint32_t dst = (k >> 5) * 4096 + sw64(c * 64 + col * 2);
        *(__nv_bfloat16*)(g_Bap_h + dst) = h;
        *(__nv_bfloat16*)(g_Bap_l + dst) = l;
    } else if (idx < K0_R3) {
        int u = idx - K0_R2;
        if (u < NU) {
            float s = sqrtf((float)((2 * NN + 1) * (2 * NN + 1) - 8 * u));
            int i = (int)(((float)(2 * NN + 1) - s) * 0.5f);
            if (i > NN - 1) i = NN - 1;
            if (i < 0) i = 0;
            while (i > 0 && i * NN - i * (i - 1) / 2 > u) i--;
            while ((i + 1) * NN - (i + 1) * i / 2 <= u) i++;
            int j = i + (u - (i * NN - i * (i - 1) / 2));
            g_pair[u] = (uint32_t)((i << 8) | j);
        } else {
            g_pair[u] = 0xFFFFFFFFu;
        }
    } else if (idx < K0_R4) {
        int c = idx - K0_R3;
        float sc = rsqrtf(v1[c] + EPSBN) * g1[c];
        g_sc1[c] = sc;
        g_of1[c] = (bll[c] - m1[c]) * sc + b1[c];
    } else if (idx < K0_R5) {
        int r = idx - K0_R4;
        int n = r >> 7, k = r & 127;
        float v = (n < 64) ? Wpa[(size_t)k * D2 + n]
                           : Wpn[(size_t)k * D2 + (n - 64)];
        __nv_bfloat16 h = __float2bfloat16(v);
        __nv_bfloat16 l = __float2bfloat16(v - __bfloat162float(h));
        uint32_t dst = (k >> 5) * 8192 + sw64(n * 64 + (k & 31) * 2);
        *(__nv_bfloat16*)(g_Byz_h + dst) = h;
        *(__nv_bfloat16*)(g_Byz_l + dst) = l;
    }
}

// ====== K1: feat @ W_ll (hi/lo bf16 3-mma) + fused maxpool3+BN1+selu =======
#define K1_SMEM 67584
__global__ __launch_bounds__(512) void k1(const float* __restrict__ feat)
{
    extern __shared__ __align__(1024) unsigned char sm1[];
    uint32_t sb = smem_u32(sm1);
    const int t = threadIdx.x, lane = t & 31, wid = t >> 5;
    const int wm = wid >> 1, wn = wid & 1;
    const int m0 = blockIdx.x * 126;

    float acc[8][4];
#pragma unroll
    for (int nf = 0; nf < 8; nf++)
#pragma unroll
        for (int q = 0; q < 4; q++) acc[nf][q] = 0.f;

    const int ar = t >> 2, ak = (t & 3) * 8;
    const int arow_g = min(m0 + ar, MTOT - 1);
    const float* fp = feat + (size_t)arow_g * DSSL + ak;
    float4 fst[2];

    auto ldgA = [&](int kt) {
        const float* p = fp + kt * 32;
        fst[0] = *(const float4*)p;
        fst[1] = *(const float4*)(p + 4);
    };
    auto stsA = [&](int buf) {
        const float* vv = (const float*)fst;
        uint32_t h[4], l[4];
#pragma unroll
        for (int q = 0; q < 4; q++) split2(vv[2 * q], vv[2 * q + 1], h[q], l[q]);
        uint32_t base = (uint32_t)buf * 32768u;
        uint32_t o = sw64(ar * 64 + ak * 2);
        *(uint4*)(sm1 + base + o)        = make_uint4(h[0], h[1], h[2], h[3]);
        *(uint4*)(sm1 + base + 8192 + o) = make_uint4(l[0], l[1], l[2], l[3]);
    };
    auto cpB = [&](int kt, int buf) {
        uint32_t dh = sb + buf * 32768 + 16384 + t * 16;
        uint32_t dl = sb + buf * 32768 + 24576 + t * 16;
        CPA16(dh, g_Bll_h + kt * 8192 + t * 16);
        CPA16(dl, g_Bll_l + kt * 8192 + t * 16);
    };
    auto compute = [&](int buf) {
        uint32_t aH = sb + buf * 32768, aL = aH + 8192;
        uint32_t bH = aH + 16384, bL = aH + 24576;
#pragma unroll
        for (int kf = 0; kf < 2; kf++) {
            uint32_t ah[4], al[4];
            uint32_t off = sw64((wm * 16 + (lane & 15)) * 64 +
                                kf * 32 + (lane >> 4) * 16);
            LDSM4(ah, aH + off);
            LDSM4(al, aL + off);
#pragma unroll
            for (int nf2 = 0; nf2 < 4; nf2++) {
                uint32_t boff = sw64((wn * 64 + nf2 * 16 + (lane & 7) +
                                      ((lane >> 4) & 1) * 8) * 64 +
                                     kf * 32 + ((lane >> 3) & 1) * 16);
                uint32_t bh[4], bl[4];
                LDSM4(bh, bH + boff);
                LDSM4(bl, bL + boff);
                float* c0 = acc[nf2 * 2];
                float* c1 = acc[nf2 * 2 + 1];
                mma_bf16(c0, ah[0], ah[1], ah[2], ah[3], bh[0], bh[1]);
                mma_bf16(c0, ah[0], ah[1], ah[2], ah[3], bl[0], bl[1]);
                mma_bf16(c0, al[0], al[1], al[2], al[3], bh[0], bh[1]);
                mma_bf16(c1, ah[0], ah[1], ah[2], ah[3], bh[2], bh[3]);
                mma_bf16(c1, ah[0], ah[1], ah[2], ah[3], bl[2], bl[3]);
                mma_bf16(c1, al[0], al[1], al[2], al[3], bh[2], bh[3]);
            }
        }
    };

    ldgA(0); cpB(0, 0); CPCOMMIT();
    stsA(0);
    CPWAIT(); __syncthreads();
    for (int kt = 0; kt < 32; kt++) {
        int cur = kt & 1;
        if (kt < 31) { ldgA(kt + 1); cpB(kt + 1, cur ^ 1); CPCOMMIT(); }
        compute(cur);
        if (kt < 31) stsA(cur ^ 1);
        CPWAIT(); __syncthreads();
    }

    float* Cep = (float*)sm1;                       // 128 x 132
    const int g = lane >> 2, tg = lane & 3;
#pragma unroll
    for (int nf = 0; nf < 8; nf++) {
        int row = wm * 16 + g;
        int col = wn * 64 + nf * 8 + tg * 2;
        Cep[row * 132 + col]           = acc[nf][0];
        Cep[row * 132 + col + 1]       = acc[nf][1];
        Cep[(row + 8) * 132 + col]     = acc[nf][2];
        Cep[(row + 8) * 132 + col + 1] = acc[nf][3];
    }
    __syncthreads();
#pragma unroll
    for (int pass = 0; pass < 11; pass++) {
        int e = t + pass * 512;
        if (e < 42 * 128) {
            int nl = e >> 7, c = e & 127;
            const float* rp = Cep + (3 * nl) * 132 + c;
            float v = fmaxf(rp[0], fmaxf(rp[132], rp[264]));
            int node = blockIdx.x * 42 + nl;
            if (node < NODES)
                g_x[(size_t)node * D1 + c] = selu_f(v * g_sc1[c] + g_of1[c]);
        }
    }
}

// ==== KY: [Y|Z] = X @ [W_pa|W_pn]  via hi/lo bf16 3-mma (k1 clone, K=128) ==
#define KY_SMEM 65536
__global__ __launch_bounds__(512) void ky()
{
    extern __shared__ __align__(1024) unsigned char smy[];
    uint32_t sb = smem_u32(smy);
    const int t = threadIdx.x, lane = t & 31, wid = t >> 5;
    const int wm = wid >> 1, wn = wid & 1;
    const int m0 = blockIdx.x * 128;

    float acc[8][4];
#pragma unroll
    for (int nf = 0; nf < 8; nf++)
#pragma unroll
        for (int q = 0; q < 4; q++) acc[nf][q] = 0.f;

    const int ar = t >> 2, ak = (t & 3) * 8;
    const float* fp = g_x + (size_t)(m0 + ar) * D1 + ak;
    float4 fst[2];

    auto ldgA = [&](int kt) {
        const float* p = fp + kt * 32;
        fst[0] = *(const float4*)p;
        fst[1] = *(const float4*)(p + 4);
    };
    auto stsA = [&](int buf) {
        const float* vv = (const float*)fst;
        uint32_t h[4], l[4];
#pragma unroll
        for (int q = 0; q < 4; q++) split2(vv[2 * q], vv[2 * q + 1], h[q], l[q]);
        uint32_t base = (uint32_t)buf * 32768u;
        uint32_t o = sw64(ar * 64 + ak * 2);
        *(uint4*)(smy + base + o)        = make_uint4(h[0], h[1], h[2], h[3]);
        *(uint4*)(smy + base + 8192 + o) = make_uint4(l[0], l[1], l[2], l[3]);
    };
    auto cpB = [&](int kt, int buf) {
        uint32_t dh = sb + buf * 32768 + 16384 + t * 16;
        uint32_t dl = sb + buf * 32768 + 24576 + t * 16;
        CPA16(dh, g_Byz_h + kt * 8192 + t * 16);
        CPA16(dl, g_Byz_l + kt * 8192 + t * 16);
    };
    auto compute = [&](int buf) {
        uint32_t aH = sb + buf * 32768, aL = aH + 8192;
        uint32_t bH = aH + 16384, bL = aH + 24576;
#pragma unroll
        for (int kf = 0; kf < 2; kf++) {
            uint32_t ah[4], al[4];
            uint32_t off = sw64((wm * 16 + (lane & 15)) * 64 +
                                kf * 32 + (lane >> 4) * 16);
            LDSM4(ah, aH + off);
            LDSM4(al, aL + off);
#pragma unroll
            for (int nf2 = 0; nf2 < 4; nf2++) {
                uint32_t boff = sw64((wn * 64 + nf2 * 16 + (lane & 7) +
                                      ((lane >> 4) & 1) * 8) * 64 +
                                     kf * 32 + ((lane >> 3) & 1) * 16);
                uint32_t bh[4], bl[4];
                LDSM4(bh, bH + boff);
                LDSM4(bl, bL + boff);
                float* c0 = acc[nf2 * 2];
                float* c1 = acc[nf2 * 2 + 1];
                mma_bf16(c0, ah[0], ah[1], ah[2], ah[3], bh[0], bh[1]);
                mma_bf16(c0, ah[0], ah[1], ah[2], ah[3], bl[0], bl[1]);
                mma_bf16(c0, al[0], al[1], al[2], al[3], bh[0], bh[1]);
                mma_bf16(c1, ah[0], ah[1], ah[2], ah[3], bh[2], bh[3]);
                mma_bf16(c1, ah[0], ah[1], ah[2], ah[3], bl[2], bl[3]);
                mma_bf16(c1, al[0], al[1], al[2], al[3], bh[2], bh[3]);
            }
        }
    };

    ldgA(0); cpB(0, 0); CPCOMMIT();
    stsA(0);
    CPWAIT(); __syncthreads();
    for (int kt = 0; kt < 4; kt++) {
        int cur = kt & 1;
        if (kt < 3) { ldgA(kt + 1); cpB(kt + 1, cur ^ 1); CPCOMMIT(); }
        compute(cur);
        if (kt < 3) stsA(cur ^ 1);
        CPWAIT(); __syncthreads();
    }

    const int g = lane >> 2, tg = lane & 3;
    float* dst = wn ? g_z : g_y;
#pragma unroll
    for (int nf = 0; nf < 8; nf++) {
        int row = m0 + wm * 16 + g;
        int col = nf * 8 + tg * 2;
        *(float2*)&dst[(size_t)row * D2 + col] =
            make_float2(acc[nf][0], acc[nf][1]);
        *(float2*)&dst[(size_t)(row + 8) * D2 + col] =
            make_float2(acc[nf][2], acc[nf][3]);
    }
}

// ====== K2: pair GEMM, warp = 32 pairs x 64 cols, sync-free loop ===========
// A frags built in registers from Xs; B read once per c16 feeds 48 MMAs.
#define O2_ATT  0
#define O2_BAP  256
#define O2_X    1536
#define O2_WH   37888
#define O2_WL   (O2_WH + 16384)
#define K2_SMEM (O2_WL + 16384)      // 70656
__global__ __launch_bounds__(256, 2) void k2(
    const float* __restrict__ bap, const float* __restrict__ attw)
{
    extern __shared__ __align__(1024) unsigned char sm2[];
    uint32_t sb = smem_u32(sm2);
    float* attS  = (float*)(sm2 + O2_ATT);
    float* bapS  = (float*)(sm2 + O2_BAP);
    float* Xs    = (float*)(sm2 + O2_X);        // 67 x 132
    const int b = blockIdx.y;
    const int t = threadIdx.x, lane = t & 31, w = t >> 5;
    const int g = lane >> 2, tg = lane & 3;

    {
        uint32_t dh = sb + O2_WH + t * 64, dl = sb + O2_WL + t * 64;
        const unsigned char* sh = g_Bap_h + t * 64;
        const unsigned char* sl = g_Bap_l + t * 64;
#pragma unroll
        for (int q = 0; q < 4; q++) {
            CPA16(dh + q * 16, sh + q * 16);
            CPA16(dl + q * 16, sl + q * 16);
        }
        CPCOMMIT();
    }
    if (t < 64) { attS[t] = attw[t]; bapS[t] = bap[t]; }
    {
        const float* xg = g_x + (size_t)b * NN * D1;
        for (int i = t; i < NN * 32; i += 256) {
            int row = i >> 5, c4 = (i & 31) * 4;
            *(float4*)(Xs + row * 132 + c4) = *(const float4*)(xg + row * D1 + c4);
        }
    }
    CPWAIT(); __syncthreads();

    float* lg = g_logit + (size_t)b * NPAIR;

    for (int tt = 0; tt < 3; tt++) {
        const int u0 = (blockIdx.x * 3 + tt) * 256;
        int   ur[4];
        uint32_t pk[4];
        const float *xi[4], *xj[4];
#pragma unroll
        for (int q = 0; q < 4; q++) {
            ur[q] = u0 + w * 32 + (q >> 1) * 16 + (q & 1) * 8 + g;
            pk[q] = g_pair[min(ur[q], NU - 1)];
            xi[q] = Xs + (pk[q] >> 8) * 132;
            xj[q] = Xs + (pk[q] & 255) * 132;
        }

        float acc[2][8][4];
#pragma unroll
        for (int mf = 0; mf < 2; mf++)
#pragma unroll
            for (int nf = 0; nf < 8; nf++)
#pragma unroll
                for (int q = 0; q < 4; q++) acc[mf][nf][q] = 0.f;

#pragma unroll
        for (int c16 = 0; c16 < 8; c16++) {
            const int kb = c16 * 16 + 4 * tg;
            uint32_t ah[2][4], al[2][4];
#pragma unroll
            for (int mf = 0; mf < 2; mf++) {
                float4 vi0 = *(const float4*)(xi[mf * 2]     + kb);
                float4 vj0 = *(const float4*)(xj[mf * 2]     + kb);
                float4 vi1 = *(const float4*)(xi[mf * 2 + 1] + kb);
                float4 vj1 = *(const float4*)(xj[mf * 2 + 1] + kb);
                split2(vi0.x * vj0.x, vi0.y * vj0.y, ah[mf][0], al[mf][0]);
                split2(vi0.z * vj0.z, vi0.w * vj0.w, ah[mf][2], al[mf][2]);
                split2(vi1.x * vj1.x, vi1.y * vj1.y, ah[mf][1], al[mf][1]);
                split2(vi1.z * vj1.z, vi1.w * vj1.w, ah[mf][3], al[mf][3]);
            }
#pragma unroll
            for (int nf2 = 0; nf2 < 4; nf2++) {
                uint32_t boff = sw64((uint32_t)((nf2 * 16 + (lane & 7) +
                                                 ((lane >> 4) & 1) * 8) * 64 +
                                                (c16 & 1) * 32 + ((lane >> 3) & 1) * 16));
                uint32_t bh[4], bl[4];
                LDSM4(bh, sb + O2_WH + (c16 >> 1) * 4096 + boff);
                LDSM4(bl, sb + O2_WL + (c16 >> 1) * 4096 + boff);
#pragma unroll
                for (int mf = 0; mf < 2; mf++) {
                    float* c0 = acc[mf][nf2 * 2];
                    float* c1 = acc[mf][nf2 * 2 + 1];
                    mma_bf16(c0, ah[mf][0], ah[mf][1], ah[mf][2], ah[mf][3], bh[0], bh[1]);
                    mma_bf16(c0, ah[mf][0], ah[mf][1], ah[mf][2], ah[mf][3], bl[0], bl[1]);
                    mma_bf16(c0, al[mf][0], al[mf][1], al[mf][2], al[mf][3], bh[0], bh[1]);
                    mma_bf16(c1, ah[mf][0], ah[mf][1], ah[mf][2], ah[mf][3], bh[2], bh[3]);
                    mma_bf16(c1, ah[mf][0], ah[mf][1], ah[mf][2], ah[mf][3], bl[2], bl[3]);
                    mma_bf16(c1, al[mf][0], al[mf][1], al[mf][2], al[mf][3], bh[2], bh[3]);
                }
            }
        }

        // epilogue: tanh + dot(att_w); reduce over tg; direct symmetric write
#pragma unroll
        for (int mf = 0; mf < 2; mf++) {
            float p0 = 0.f, p1 = 0.f;
#pragma unroll
            for (int nf = 0; nf < 8; nf++) {
                int col = nf * 8 + tg * 2;
                float w0 = attS[col], w1 = attS[col + 1];
                float q0 = bapS[col], q1 = bapS[col + 1];
                p0 += w0 * tanh_f(acc[mf][nf][0] + q0) + w1 * tanh_f(acc[mf][nf][1] + q1);
                p1 += w0 * tanh_f(acc[mf][nf][2] + q0) + w1 * tanh_f(acc[mf][nf][3] + q1);
            }
            p0 += __shfl_xor_sync(0xffffffffu, p0, 1);
            p0 += __shfl_xor_sync(0xffffffffu, p0, 2);
            p1 += __shfl_xor_sync(0xffffffffu, p1, 1);
            p1 += __shfl_xor_sync(0xffffffffu, p1, 2);
            if (tg == 0) {
                if (ur[mf * 2] < NU) {
                    int i2 = (int)(pk[mf * 2] >> 8), j2 = (int)(pk[mf * 2] & 255);
                    lg[i2 * NN + j2] = p0;
                    lg[j2 * NN + i2] = p0;
                }
                if (ur[mf * 2 + 1] < NU) {
                    int i2 = (int)(pk[mf * 2 + 1] >> 8), j2 = (int)(pk[mf * 2 + 1] & 255);
                    lg[i2 * NN + j2] = p1;
                    lg[j2 * NN + i2] = p1;
                }
            }
        }
    }
}

// ==== K2C: softmax + h=selu(BN2(att@Y+Z+b)) + score + top-k + head =========
__global__ __launch_bounds__(256) void k2c(
    const float* __restrict__ bpa, const float* __restrict__ bpn,
    const float* __restrict__ g2, const float* __restrict__ b2,
    const float* __restrict__ m2, const float* __restrict__ v2,
    const float* __restrict__ Wpool, const float* __restrict__ bpool,
    const float* __restrict__ Wproj, const float* __restrict__ bproj,
    const float* __restrict__ Wnode, const float* __restrict__ bnode,
    float* __restrict__ out)
{
    __shared__ float Ys[NN * 68];
    __shared__ float attS[8][68];
    __shared__ float hS[NN * 64];
    __shared__ float scS[NN];
    __shared__ int   sel[NP];
    __shared__ float pv[NP];
    int b = blockIdx.x, t = threadIdx.x;
    int w = t >> 5, l = t & 31;

    for (int i = t; i < NN * 16; i += 256) {
        int row = i >> 4, q = i & 15;
        *(float4*)(Ys + row * 68 + q * 4) =
            *(const float4*)(g_y + ((size_t)b * NN + row) * D2 + q * 4);
    }
    __syncthreads();

    const int c0 = l, c1 = l + 32;
    const float bb0 = bpa[c0] + bpn[c0], bb1 = bpa[c1] + bpn[c1];
    const float s0 = rsqrtf(v2[c0] + EPSBN) * g2[c0];
    const float s1 = rsqrtf(v2[c1] + EPSBN) * g2[c1];
    const float m0 = m2[c0], m1v = m2[c1];
    const float o0 = b2[c0], o1 = b2[c1];
    const float wp0 = Wpool[c0], wp1 = Wpool[c1];
    const float bp = bpool[0];

    for (int i = w; i < NN; i += 8) {
        const float* lr = g_logit + (size_t)b * NPAIR + i * NN;
        float v0 = lr[l];
        float v1 = lr[l + 32];
        float vv2 = (l < 3) ? lr[l + 64] : -1e30f;
        float mx = fmaxf(v0, fmaxf(v1, vv2));
#pragma unroll
        for (int o = 16; o > 0; o >>= 1) mx = fmaxf(mx, __shfl_xor_sync(0xffffffffu, mx, o));
        float e0 = __expf(v0 - mx);
        float e1 = __expf(v1 - mx);
        float e2 = (l < 3) ? __expf(vv2 - mx) : 0.f;
        float ss = e0 + e1 + e2;
#pragma unroll
        for (int o = 16; o > 0; o >>= 1) ss += __shfl_xor_sync(0xffffffffu, ss, o);
        float inv = 1.f / ss;
        attS[w][l] = e0 * inv;
        attS[w][l + 32] = e1 * inv;
        if (l < 3) attS[w][l + 64] = e2 * inv;
        __syncwarp();

        float a0 = 0.f, a1 = 0.f;
        for (int j = 0; j < NN; j++) {
            float a = attS[w][j];
            a0 += a * Ys[j * 68 + c0];
            a1 += a * Ys[j * 68 + c1];
        }
        size_t zb = ((size_t)b * NN + i) * D2;
        float u0 = a0 + g_z[zb + c0] + bb0;
        float u1 = a1 + g_z[zb + c1] + bb1;
        u0 = selu_f((u0 - m0) * s0 + o0);
        u1 = selu_f((u1 - m1v) * s1 + o1);
        hS[i * 64 + c0] = u0;
        hS[i * 64 + c1] = u1;
        float sp = u0 * wp0 + u1 * wp1;
#pragma unroll
        for (int o = 16; o > 0; o >>= 1) sp += __shfl_xor_sync(0xffffffffu, sp, o);
        if (l == 0) scS[i] = 1.f / (1.f + expf(-(sp + bp)));
        __syncwarp();
    }
    __syncthreads();

    // ---- exact stable top-k(53) ----
    if (t < NN) {
        float st = scS[t]; int rank = 0;
        for (int j = 0; j < NN; j++) {
            float sj = scS[j];
            rank += (sj > st) || (sj == st && j < t);
        }
        if (rank < NP) sel[rank] = t;
    }
    __syncthreads();

    for (int p = w; p < NP; p += 8) {
        int node = sel[p];
        float d = hS[node * 64 + l] * Wproj[l] + hS[node * 64 + 32 + l] * Wproj[l + 32];
#pragma unroll
        for (int o = 16; o > 0; o >>= 1) d += __shfl_xor_sync(0xffffffffu, d, o);
        if (l == 0) pv[p] = scS[node] * d + bproj[0];
    }
    __syncthreads();
    if (t < 2) {
        float o = bnode[t];
        for (int p = 0; p < NP; p++) o += pv[p] * Wnode[p * 2 + t];
        out[b * 2 + t] = o;
    }
}

// ===========================================================================
extern "C" void kernel_launch(void* const* d_in, const int* in_sizes, int n_in,
                              void* d_out, int out_size)
{
    const float* feat  = (const float*)d_in[0];
    const float* Wll   = (const float*)d_in[1];
    const float* bll   = (const float*)d_in[2];
    const float* bn1g  = (const float*)d_in[3];
    const float* bn1b  = (const float*)d_in[4];
    const float* bn1m  = (const float*)d_in[5];
    const float* bn1v  = (const float*)d_in[6];
    const float* Wap   = (const float*)d_in[7];
    const float* bap   = (const float*)d_in[8];
    const float* attw  = (const float*)d_in[9];
    const float* Wpa   = (const float*)d_in[10];
    const float* bpa   = (const float*)d_in[11];
    const float* Wpn   = (const float*)d_in[12];
    const float* bpn   = (const float*)d_in[13];
    const float* bn2g  = (const float*)d_in[14];
    const float* bn2b  = (const float*)d_in[15];
    const float* bn2m  = (const float*)d_in[16];
    const float* bn2v  = (const float*)d_in[17];
    const float* Wpool = (const float*)d_in[18];
    const float* bpool = (const float*)d_in[19];
    const float* Wproj = (const float*)d_in[20];
    const float* bproj = (const float*)d_in[21];
    const float* Wnode = (const float*)d_in[22];
    const float* bnode = (const float*)d_in[23];

    cudaFuncSetAttribute(k1, cudaFuncAttributeMaxDynamicSharedMemorySize, K1_SMEM);
    cudaFuncSetAttribute(ky, cudaFuncAttributeMaxDynamicSharedMemorySize, KY_SMEM);
    cudaFuncSetAttribute(k2, cudaFuncAttributeMaxDynamicSharedMemorySize, K2_SMEM);

    k0 <<<(K0_R5 + 255) / 256, 256>>>(Wll, Wap, bll, bn1g, bn1b, bn1m, bn1v,
                                      Wpa, Wpn);
    k1 <<<(MTOT + 125) / 126, 512, K1_SMEM>>>(feat);
    ky <<<NODES / 128, 512, KY_SMEM>>>();
    k2 <<<dim3(3, BS), 256, K2_SMEM>>>(bap, attw);
    k2c<<<BS, 256>>>(bpa, bpn, bn2g, bn2b, bn2m, bn2v, Wpool, bpool,
                     Wproj, bproj, Wnode, bnode, (float*)d_out);
}

// round 15
// speedup vs baseline: 1.1038x; 1.1038x over previous
#include <cuda_runtime.h>
#include <cuda_bf16.h>
#include <math.h>
#include <stdint.h>

#define BS   256
#define SEQ  201
#define DSSL 1024
#define D1   128
#define D2   64
#define NN   67
#define NP   53
#define NPAIR (NN*NN)      // 4489
#define NU   2278          // upper-triangle pairs (i<=j)
#define NUT  2304
#define EPSBN 1e-5f
#define MTOT  (BS*SEQ)     // 51456
#define NODES (BS*NN)      // 17152 = 134*128

// ---------------- scratch (device globals; no runtime allocation) ----------
__device__ float g_x [NODES * D1];
__device__ float g_y [NODES * D2];         // X @ W_pa
__device__ float g_z [NODES * D2];         // X @ W_pn
__device__ float g_logit[BS * NPAIR];
__device__ uint32_t g_pair[NUT];           // packed (i<<8)|j upper-tri table
__device__ float g_sc1[D1], g_of1[D1];     // folded bias+BN1 scale/offset
// pre-swizzled (SW64, 64B rows) pre-split bf16 weight images
__device__ __align__(16) unsigned char g_Bll_h[32 * 8192];
__device__ __align__(16) unsigned char g_Bll_l[32 * 8192];
__device__ __align__(16) unsigned char g_Bap_h[4 * 4096];   // k-slot-permuted
__device__ __align__(16) unsigned char g_Bap_l[4 * 4096];
__device__ __align__(16) unsigned char g_Byz_h[4 * 8192];   // [W_pa|W_pn]^T
__device__ __align__(16) unsigned char g_Byz_l[4 * 8192];

// ------------------------------ helpers ------------------------------------
__device__ __forceinline__ float selu_f(float v) {
    const float a = 1.6732632423543772f, s = 1.0507009873554805f;
    return v > 0.f ? s * v : s * a * expm1f(v);
}
__device__ __forceinline__ float tanh_f(float x) {
    float e = __expf(2.0f * x);
    return 1.0f - __fdividef(2.0f, e + 1.0f);
}
__host__ __device__ __forceinline__ uint32_t sw64(uint32_t o) {
    return o ^ ((o >> 3) & 0x30);
}
__device__ __forceinline__ uint32_t smem_u32(const void* p) {
    uint32_t a;
    asm("{ .reg .u64 t; cvta.to.shared.u64 t, %1; cvt.u32.u64 %0, t; }"
        : "=r"(a) : "l"(p));
    return a;
}
__device__ __forceinline__ void split2(float v0, float v1, uint32_t& h, uint32_t& l) {
    __nv_bfloat162 hp, lp;
    hp.x = __float2bfloat16(v0);  hp.y = __float2bfloat16(v1);
    lp.x = __float2bfloat16(v0 - __bfloat162float(hp.x));
    lp.y = __float2bfloat16(v1 - __bfloat162float(hp.y));
    h = *reinterpret_cast<uint32_t*>(&hp);
    l = *reinterpret_cast<uint32_t*>(&lp);
}
__device__ __forceinline__ void mma_bf16(float* c,
    uint32_t a0, uint32_t a1, uint32_t a2, uint32_t a3,
    uint32_t b0, uint32_t b1)
{
    asm volatile(
      "mma.sync.aligned.m16n8k16.row.col.f32.bf16.bf16.f32 "
      "{%0,%1,%2,%3},{%4,%5,%6,%7},{%8,%9},{%0,%1,%2,%3};\n"
      : "+f"(c[0]), "+f"(c[1]), "+f"(c[2]), "+f"(c[3])
      : "r"(a0), "r"(a1), "r"(a2), "r"(a3), "r"(b0), "r"(b1));
}
#define LDSM4(r, a) \
    asm volatile("ldmatrix.sync.aligned.m8n8.x4.shared.b16 {%0,%1,%2,%3}, [%4];" \
        : "=r"((r)[0]), "=r"((r)[1]), "=r"((r)[2]), "=r"((r)[3]) : "r"(a))
#define CPA16(d, s) \
    asm volatile("cp.async.ca.shared.global [%0], [%1], 16;" :: "r"(d), "l"(s))
#define CPCOMMIT() asm volatile("cp.async.commit_group;" ::: "memory")
#define CPWAIT()   asm volatile("cp.async.wait_group 0;" ::: "memory")

// ========= K0: weight prep (split+swizzle), pair table, BN1 fold ===========
#define K0_R1 (D1*DSSL)
#define K0_R2 (K0_R1 + D1*D2)
#define K0_R3 (K0_R2 + NUT)
#define K0_R4 (K0_R3 + D1)
#define K0_R5 (K0_R4 + D1*D1)
__global__ void k0(const float* __restrict__ Wll, const float* __restrict__ Wap,
                   const float* __restrict__ bll, const float* __restrict__ g1,
                   const float* __restrict__ b1,  const float* __restrict__ m1,
                   const float* __restrict__ v1,
                   const float* __restrict__ Wpa, const float* __restrict__ Wpn)
{
    int idx = blockIdx.x * 256 + threadIdx.x;
    if (idx < K0_R1) {
        int n = idx >> 10, k = idx & 1023;
        float v = Wll[(size_t)k * D1 + n];
        __nv_bfloat16 h = __float2bfloat16(v);
        __nv_bfloat16 l = __float2bfloat16(v - __bfloat162float(h));
        uint32_t dst = (k >> 5) * 8192 + sw64(n * 64 + (k & 31) * 2);
        *(__nv_bfloat16*)(g_Bll_h + dst) = h;
        *(__nv_bfloat16*)(g_Bll_l + dst) = l;
    } else if (idx < K0_R2) {
        int r = idx - K0_R1;
        int k = r >> 6, c = r & 63;
        float v = Wap[(size_t)k * D2 + c];
        __nv_bfloat16 h = __float2bfloat16(v);
        __nv_bfloat16 l = __float2bfloat16(v - __bfloat162float(h));
        int kk = k & 15;
        int s = 2 * (kk >> 2) + (kk & 1) + 8 * ((kk >> 1) & 1);
        uint32_t col = (uint32_t)(((k >> 4) & 1) * 16 + s);
        uint32_t dst = (k >> 5) * 4096 + sw64(c * 64 + col * 2);
        *(__nv_bfloat16*)(g_Bap_h + dst) = h;
        *(__nv_bfloat16*)(g_Bap_l + dst) = l;
    } else if (idx < K0_R3) {
        int u = idx - K0_R2;
        if (u < NU) {
            float s = sqrtf((float)((2 * NN + 1) * (2 * NN + 1) - 8 * u));
            int i = (int)(((float)(2 * NN + 1) - s) * 0.5f);
            if (i > NN - 1) i = NN - 1;
            if (i < 0) i = 0;
            while (i > 0 && i * NN - i * (i - 1) / 2 > u) i--;
            while ((i + 1) * NN - (i + 1) * i / 2 <= u) i++;
            int j = i + (u - (i * NN - i * (i - 1) / 2));
            g_pair[u] = (uint32_t)((i << 8) | j);
        } else {
            g_pair[u] = 0xFFFFFFFFu;
        }
    } else if (idx < K0_R4) {
        int c = idx - K0_R3;
        float sc = rsqrtf(v1[c] + EPSBN) * g1[c];
        g_sc1[c] = sc;
        g_of1[c] = (bll[c] - m1[c]) * sc + b1[c];
    } else if (idx < K0_R5) {
        int r = idx - K0_R4;
        int n = r >> 7, k = r & 127;
        float v = (n < 64) ? Wpa[(size_t)k * D2 + n]
                           : Wpn[(size_t)k * D2 + (n - 64)];
        __nv_bfloat16 h = __float2bfloat16(v);
        __nv_bfloat16 l = __float2bfloat16(v - __bfloat162float(h));
        uint32_t dst = (k >> 5) * 8192 + sw64(n * 64 + (k & 31) * 2);
        *(__nv_bfloat16*)(g_Byz_h + dst) = h;
        *(__nv_bfloat16*)(g_Byz_l + dst) = l;
    }
}

// ====== K1: feat @ W_ll (hi/lo bf16 3-mma) + fused maxpool3+BN1+selu =======
// BK=64 per outer iteration as two BK=32 sub-tiles -> 16 syncs instead of 32.
// smem: 2 big buffers x 64KB (sub0/sub1 each AH,AL,BH,BL 8KB).
#define K1_SMEM 131072
__global__ __launch_bounds__(512) void k1(const float* __restrict__ feat)
{
    extern __shared__ __align__(1024) unsigned char sm1[];
    uint32_t sb = smem_u32(sm1);
    const int t = threadIdx.x, lane = t & 31, wid = t >> 5;
    const int wm = wid >> 1, wn = wid & 1;
    const int m0 = blockIdx.x * 126;

    float acc[8][4];
#pragma unroll
    for (int nf = 0; nf < 8; nf++)
#pragma unroll
        for (int q = 0; q < 4; q++) acc[nf][q] = 0.f;

    const int ar = t >> 2, ak = (t & 3) * 8;
    const int arow_g = min(m0 + ar, MTOT - 1);
    const float* fp = feat + (size_t)arow_g * DSSL + ak;
    float4 fst[4];

    auto ldgA = [&](int kt2) {
        const float* p = fp + kt2 * 64;
        fst[0] = *(const float4*)p;
        fst[1] = *(const float4*)(p + 4);
        fst[2] = *(const float4*)(p + 32);
        fst[3] = *(const float4*)(p + 36);
    };
    auto stsA = [&](int buf) {
        uint32_t o = sw64(ar * 64 + ak * 2);
#pragma unroll
        for (int s = 0; s < 2; s++) {
            const float* vv = (const float*)(fst + s * 2);
            uint32_t h[4], l[4];
#pragma unroll
            for (int q = 0; q < 4; q++) split2(vv[2 * q], vv[2 * q + 1], h[q], l[q]);
            uint32_t base = (uint32_t)buf * 65536u + (uint32_t)s * 32768u;
            *(uint4*)(sm1 + base + o)        = make_uint4(h[0], h[1], h[2], h[3]);
            *(uint4*)(sm1 + base + 8192 + o) = make_uint4(l[0], l[1], l[2], l[3]);
        }
    };
    auto cpB = [&](int kt2, int buf) {
#pragma unroll
        for (int s = 0; s < 2; s++) {
            uint32_t base = sb + buf * 65536 + s * 32768;
            int kt = kt2 * 2 + s;
            CPA16(base + 16384 + t * 16, g_Bll_h + kt * 8192 + t * 16);
            CPA16(base + 24576 + t * 16, g_Bll_l + kt * 8192 + t * 16);
        }
    };
    auto compute = [&](int buf, int s) {
        uint32_t aH = sb + buf * 65536 + s * 32768, aL = aH + 8192;
        uint32_t bH = aH + 16384, bL = aH + 24576;
#pragma unroll
        for (int kf = 0; kf < 2; kf++) {
            uint32_t ah[4], al[4];
            uint32_t off = sw64((wm * 16 + (lane & 15)) * 64 +
                                kf * 32 + (lane >> 4) * 16);
            LDSM4(ah, aH + off);
            LDSM4(al, aL + off);
#pragma unroll
            for (int nf2 = 0; nf2 < 4; nf2++) {
                uint32_t boff = sw64((wn * 64 + nf2 * 16 + (lane & 7) +
                                      ((lane >> 4) & 1) * 8) * 64 +
                                     kf * 32 + ((lane >> 3) & 1) * 16);
                uint32_t bh[4], bl[4];
                LDSM4(bh, bH + boff);
                LDSM4(bl, bL + boff);
                float* c0 = acc[nf2 * 2];
                float* c1 = acc[nf2 * 2 + 1];
                mma_bf16(c0, ah[0], ah[1], ah[2], ah[3], bh[0], bh[1]);
                mma_bf16(c0, ah[0], ah[1], ah[2], ah[3], bl[0], bl[1]);
                mma_bf16(c0, al[0], al[1], al[2], al[3], bh[0], bh[1]);
                mma_bf16(c1, ah[0], ah[1], ah[2], ah[3], bh[2], bh[3]);
                mma_bf16(c1, ah[0], ah[1], ah[2], ah[3], bl[2], bl[3]);
                mma_bf16(c1, al[0], al[1], al[2], al[3], bh[2], bh[3]);
            }
        }
    };

    ldgA(0); cpB(0, 0); CPCOMMIT();
    stsA(0);
    CPWAIT(); __syncthreads();
    for (int kt2 = 0; kt2 < 16; kt2++) {
        int cur = kt2 & 1;
        if (kt2 < 15) { ldgA(kt2 + 1); cpB(kt2 + 1, cur ^ 1); CPCOMMIT(); }
        compute(cur, 0);
        compute(cur, 1);
        if (kt2 < 15) stsA(cur ^ 1);
        CPWAIT(); __syncthreads();
    }

    float* Cep = (float*)sm1;                       // 128 x 132
    const int g = lane >> 2, tg = lane & 3;
#pragma unroll
    for (int nf = 0; nf < 8; nf++) {
        int row = wm * 16 + g;
        int col = wn * 64 + nf * 8 + tg * 2;
        Cep[row * 132 + col]           = acc[nf][0];
        Cep[row * 132 + col + 1]       = acc[nf][1];
        Cep[(row + 8) * 132 + col]     = acc[nf][2];
        Cep[(row + 8) * 132 + col + 1] = acc[nf][3];
    }
    __syncthreads();
#pragma unroll
    for (int pass = 0; pass < 11; pass++) {
        int e = t + pass * 512;
        if (e < 42 * 128) {
            int nl = e >> 7, c = e & 127;
            const float* rp = Cep + (3 * nl) * 132 + c;
            float v = fmaxf(rp[0], fmaxf(rp[132], rp[264]));
            int node = blockIdx.x * 42 + nl;
            if (node < NODES)
                g_x[(size_t)node * D1 + c] = selu_f(v * g_sc1[c] + g_of1[c]);
        }
    }
}

// ==== KY: [Y|Z] = X @ [W_pa|W_pn]  via hi/lo bf16 3-mma (K=128) ============
#define KY_SMEM 65536
__global__ __launch_bounds__(512) void ky()
{
    extern __shared__ __align__(1024) unsigned char smy[];
    uint32_t sb = smem_u32(smy);
    const int t = threadIdx.x, lane = t & 31, wid = t >> 5;
    const int wm = wid >> 1, wn = wid & 1;
    const int m0 = blockIdx.x * 128;

    float acc[8][4];
#pragma unroll
    for (int nf = 0; nf < 8; nf++)
#pragma unroll
        for (int q = 0; q < 4; q++) acc[nf][q] = 0.f;

    const int ar = t >> 2, ak = (t & 3) * 8;
    const float* fp = g_x + (size_t)(m0 + ar) * D1 + ak;
    float4 fst[2];

    auto ldgA = [&](int kt) {
        const float* p = fp + kt * 32;
        fst[0] = *(const float4*)p;
        fst[1] = *(const float4*)(p + 4);
    };
    auto stsA = [&](int buf) {
        const float* vv = (const float*)fst;
        uint32_t h[4], l[4];
#pragma unroll
        for (int q = 0; q < 4; q++) split2(vv[2 * q], vv[2 * q + 1], h[q], l[q]);
        uint32_t base = (uint32_t)buf * 32768u;
        uint32_t o = sw64(ar * 64 + ak * 2);
        *(uint4*)(smy + base + o)        = make_uint4(h[0], h[1], h[2], h[3]);
        *(uint4*)(smy + base + 8192 + o) = make_uint4(l[0], l[1], l[2], l[3]);
    };
    auto cpB = [&](int kt, int buf) {
        uint32_t dh = sb + buf * 32768 + 16384 + t * 16;
        uint32_t dl = sb + buf * 32768 + 24576 + t * 16;
        CPA16(dh, g_Byz_h + kt * 8192 + t * 16);
        CPA16(dl, g_Byz_l + kt * 8192 + t * 16);
    };
    auto compute = [&](int buf) {
        uint32_t aH = sb + buf * 32768, aL = aH + 8192;
        uint32_t bH = aH + 16384, bL = aH + 24576;
#pragma unroll
        for (int kf = 0; kf < 2; kf++) {
            uint32_t ah[4], al[4];
            uint32_t off = sw64((wm * 16 + (lane & 15)) * 64 +
                                kf * 32 + (lane >> 4) * 16);
            LDSM4(ah, aH + off);
            LDSM4(al, aL + off);
#pragma unroll
            for (int nf2 = 0; nf2 < 4; nf2++) {
                uint32_t boff = sw64((wn * 64 + nf2 * 16 + (lane & 7) +
                                      ((lane >> 4) & 1) * 8) * 64 +
                                     kf * 32 + ((lane >> 3) & 1) * 16);
                uint32_t bh[4], bl[4];
                LDSM4(bh, bH + boff);
                LDSM4(bl, bL + boff);
                float* c0 = acc[nf2 * 2];
                float* c1 = acc[nf2 * 2 + 1];
                mma_bf16(c0, ah[0], ah[1], ah[2], ah[3], bh[0], bh[1]);
                mma_bf16(c0, ah[0], ah[1], ah[2], ah[3], bl[0], bl[1]);
                mma_bf16(c0, al[0], al[1], al[2], al[3], bh[0], bh[1]);
                mma_bf16(c1, ah[0], ah[1], ah[2], ah[3], bh[2], bh[3]);
                mma_bf16(c1, ah[0], ah[1], ah[2], ah[3], bl[2], bl[3]);
                mma_bf16(c1, al[0], al[1], al[2], al[3], bh[2], bh[3]);
            }
        }
    };

    ldgA(0); cpB(0, 0); CPCOMMIT();
    stsA(0);
    CPWAIT(); __syncthreads();
    for (int kt = 0; kt < 4; kt++) {
        int cur = kt & 1;
        if (kt < 3) { ldgA(kt + 1); cpB(kt + 1, cur ^ 1); CPCOMMIT(); }
        compute(cur);
        if (kt < 3) stsA(cur ^ 1);
        CPWAIT(); __syncthreads();
    }

    const int g = lane >> 2, tg = lane & 3;
    float* dst = wn ? g_z : g_y;
#pragma unroll
    for (int nf = 0; nf < 8; nf++) {
        int row = m0 + wm * 16 + g;
        int col = nf * 8 + tg * 2;
        *(float2*)&dst[(size_t)row * D2 + col] =
            make_float2(acc[nf][0], acc[nf][1]);
        *(float2*)&dst[(size_t)(row + 8) * D2 + col] =
            make_float2(acc[nf][2], acc[nf][3]);
    }
}

// ====== K2: pair GEMM, warp = 16 pairs x 64 cols, fully sync-free loop =====
// (R13 structure — measured best: 97.2us, 118 regs)
#define O2_ATT  0
#define O2_BAP  256
#define O2_X    1536
#define O2_WH   37888
#define O2_WL   (O2_WH + 16384)
#define K2_SMEM (O2_WL + 16384)      // 70656
__global__ __launch_bounds__(256, 2) void k2(
    const float* __restrict__ bap, const float* __restrict__ attw)
{
    extern __shared__ __align__(1024) unsigned char sm2[];
    uint32_t sb = smem_u32(sm2);
    float* attS  = (float*)(sm2 + O2_ATT);
    float* bapS  = (float*)(sm2 + O2_BAP);
    float* Xs    = (float*)(sm2 + O2_X);        // 67 x 132
    const int b = blockIdx.y;
    const int t = threadIdx.x, lane = t & 31, w = t >> 5;
    const int g = lane >> 2, tg = lane & 3;

    {
        uint32_t dh = sb + O2_WH + t * 64, dl = sb + O2_WL + t * 64;
        const unsigned char* sh = g_Bap_h + t * 64;
        const unsigned char* sl = g_Bap_l + t * 64;
#pragma unroll
        for (int q = 0; q < 4; q++) {
            CPA16(dh + q * 16, sh + q * 16);
            CPA16(dl + q * 16, sl + q * 16);
        }
        CPCOMMIT();
    }
    if (t < 64) { attS[t] = attw[t]; bapS[t] = bap[t]; }
    {
        const float* xg = g_x + (size_t)b * NN * D1;
        for (int i = t; i < NN * 32; i += 256) {
            int row = i >> 5, c4 = (i & 31) * 4;
            *(float4*)(Xs + row * 132 + c4) = *(const float4*)(xg + row * D1 + c4);
        }
    }
    CPWAIT(); __syncthreads();

    float* lg = g_logit + (size_t)b * NPAIR;

    for (int tt = 0; tt < 3; tt++) {
        const int u0 = (blockIdx.x * 3 + tt) * 128;
        const int ur0 = u0 + w * 16 + g;
        const int ur1 = ur0 + 8;
        const uint32_t pk0 = g_pair[min(ur0, NU - 1)];
        const uint32_t pk1 = g_pair[min(ur1, NU - 1)];
        const float* xi0 = Xs + (pk0 >> 8) * 132;
        const float* xj0 = Xs + (pk0 & 255) * 132;
        const float* xi1 = Xs + (pk1 >> 8) * 132;
        const float* xj1 = Xs + (pk1 & 255) * 132;

        float acc[8][4];
#pragma unroll
        for (int nf = 0; nf < 8; nf++)
#pragma unroll
            for (int q = 0; q < 4; q++) acc[nf][q] = 0.f;

#pragma unroll
        for (int c16 = 0; c16 < 8; c16++) {
            const int kb = c16 * 16 + 4 * tg;
            float4 vi0 = *(const float4*)(xi0 + kb);
            float4 vj0 = *(const float4*)(xj0 + kb);
            float4 vi1 = *(const float4*)(xi1 + kb);
            float4 vj1 = *(const float4*)(xj1 + kb);
            uint32_t a0h, a0l, a1h, a1l, a2h, a2l, a3h, a3l;
            split2(vi0.x * vj0.x, vi0.y * vj0.y, a0h, a0l);
            split2(vi0.z * vj0.z, vi0.w * vj0.w, a2h, a2l);
            split2(vi1.x * vj1.x, vi1.y * vj1.y, a1h, a1l);
            split2(vi1.z * vj1.z, vi1.w * vj1.w, a3h, a3l);
#pragma unroll
            for (int nf2 = 0; nf2 < 4; nf2++) {
                uint32_t boff = sw64((uint32_t)((nf2 * 16 + (lane & 7) +
                                                 ((lane >> 4) & 1) * 8) * 64 +
                                                (c16 & 1) * 32 + ((lane >> 3) & 1) * 16));
                uint32_t bh[4], bl[4];
                LDSM4(bh, sb + O2_WH + (c16 >> 1) * 4096 + boff);
                LDSM4(bl, sb + O2_WL + (c16 >> 1) * 4096 + boff);
                float* c0 = acc[nf2 * 2];
                float* c1 = acc[nf2 * 2 + 1];
                mma_bf16(c0, a0h, a1h, a2h, a3h, bh[0], bh[1]);
                mma_bf16(c0, a0h, a1h, a2h, a3h, bl[0], bl[1]);
                mma_bf16(c0, a0l, a1l, a2l, a3l, bh[0], bh[1]);
                mma_bf16(c1, a0h, a1h, a2h, a3h, bh[2], bh[3]);
                mma_bf16(c1, a0h, a1h, a2h, a3h, bl[2], bl[3]);
                mma_bf16(c1, a0l, a1l, a2l, a3l, bh[2], bh[3]);
            }
        }

        float p0 = 0.f, p1 = 0.f;
#pragma unroll
        for (int nf = 0; nf < 8; nf++) {
            int col = nf * 8 + tg * 2;
            float w0 = attS[col], w1 = attS[col + 1];
            float q0 = bapS[col], q1 = bapS[col + 1];
            p0 += w0 * tanh_f(acc[nf][0] + q0) + w1 * tanh_f(acc[nf][1] + q1);
            p1 += w0 * tanh_f(acc[nf][2] + q0) + w1 * tanh_f(acc[nf][3] + q1);
        }
        p0 += __shfl_xor_sync(0xffffffffu, p0, 1);
        p0 += __shfl_xor_sync(0xffffffffu, p0, 2);
        p1 += __shfl_xor_sync(0xffffffffu, p1, 1);
        p1 += __shfl_xor_sync(0xffffffffu, p1, 2);
        if (tg == 0) {
            if (ur0 < NU) {
                int i2 = (int)(pk0 >> 8), j2 = (int)(pk0 & 255);
                lg[i2 * NN + j2] = p0;
                lg[j2 * NN + i2] = p0;
            }
            if (ur1 < NU) {
                int i2 = (int)(pk1 >> 8), j2 = (int)(pk1 & 255);
                lg[i2 * NN + j2] = p1;
                lg[j2 * NN + i2] = p1;
            }
        }
    }
}

// ==== K2C: softmax + h=selu(BN2(att@Y+Z+b)) + score + top-k + head =========
__global__ __launch_bounds__(256) void k2c(
    const float* __restrict__ bpa, const float* __restrict__ bpn,
    const float* __restrict__ g2, const float* __restrict__ b2,
    const float* __restrict__ m2, const float* __restrict__ v2,
    const float* __restrict__ Wpool, const float* __restrict__ bpool,
    const float* __restrict__ Wproj, const float* __restrict__ bproj,
    const float* __restrict__ Wnode, const float* __restrict__ bnode,
    float* __restrict__ out)
{
    __shared__ float Ys[NN * 68];
    __shared__ float attS[8][68];
    __shared__ float hS[NN * 64];
    __shared__ float scS[NN];
    __shared__ int   sel[NP];
    __shared__ float pv[NP];
    int b = blockIdx.x, t = threadIdx.x;
    int w = t >> 5, l = t & 31;

    for (int i = t; i < NN * 16; i += 256) {
        int row = i >> 4, q = i & 15;
        *(float4*)(Ys + row * 68 + q * 4) =
            *(const float4*)(g_y + ((size_t)b * NN + row) * D2 + q * 4);
    }
    __syncthreads();

    const int c0 = l, c1 = l + 32;
    const float bb0 = bpa[c0] + bpn[c0], bb1 = bpa[c1] + bpn[c1];
    const float s0 = rsqrtf(v2[c0] + EPSBN) * g2[c0];
    const float s1 = rsqrtf(v2[c1] + EPSBN) * g2[c1];
    const float m0 = m2[c0], m1v = m2[c1];
    const float o0 = b2[c0], o1 = b2[c1];
    const float wp0 = Wpool[c0], wp1 = Wpool[c1];
    const float bp = bpool[0];

    for (int i = w; i < NN; i += 8) {
        const float* lr = g_logit + (size_t)b * NPAIR + i * NN;
        float v0 = lr[l];
        float v1 = lr[l + 32];
        float vv2 = (l < 3) ? lr[l + 64] : -1e30f;
        float mx = fmaxf(v0, fmaxf(v1, vv2));
#pragma unroll
        for (int o = 16; o > 0; o >>= 1) mx = fmaxf(mx, __shfl_xor_sync(0xffffffffu, mx, o));
        float e0 = __expf(v0 - mx);
        float e1 = __expf(v1 - mx);
        float e2 = (l < 3) ? __expf(vv2 - mx) : 0.f;
        float ss = e0 + e1 + e2;
#pragma unroll
        for (int o = 16; o > 0; o >>= 1) ss += __shfl_xor_sync(0xffffffffu, ss, o);
        float inv = 1.f / ss;
        attS[w][l] = e0 * inv;
        attS[w][l + 32] = e1 * inv;
        if (l < 3) attS[w][l + 64] = e2 * inv;
        __syncwarp();

        float a0 = 0.f, a1 = 0.f;
        for (int j = 0; j < NN; j++) {
            float a = attS[w][j];
            a0 += a * Ys[j * 68 + c0];
            a1 += a * Ys[j * 68 + c1];
        }
        size_t zb = ((size_t)b * NN + i) * D2;
        float u0 = a0 + g_z[zb + c0] + bb0;
        float u1 = a1 + g_z[zb + c1] + bb1;
        u0 = selu_f((u0 - m0) * s0 + o0);
        u1 = selu_f((u1 - m1v) * s1 + o1);
        hS[i * 64 + c0] = u0;
        hS[i * 64 + c1] = u1;
        float sp = u0 * wp0 + u1 * wp1;
#pragma unroll
        for (int o = 16; o > 0; o >>= 1) sp += __shfl_xor_sync(0xffffffffu, sp, o);
        if (l == 0) scS[i] = 1.f / (1.f + expf(-(sp + bp)));
        __syncwarp();
    }
    __syncthreads();

    if (t < NN) {
        float st = scS[t]; int rank = 0;
        for (int j = 0; j < NN; j++) {
            float sj = scS[j];
            rank += (sj > st) || (sj == st && j < t);
        }
        if (rank < NP) sel[rank] = t;
    }
    __syncthreads();

    for (int p = w; p < NP; p += 8) {
        int node = sel[p];
        float d = hS[node * 64 + l] * Wproj[l] + hS[node * 64 + 32 + l] * Wproj[l + 32];
#pragma unroll
        for (int o = 16; o > 0; o >>= 1) d += __shfl_xor_sync(0xffffffffu, d, o);
        if (l == 0) pv[p] = scS[node] * d + bproj[0];
    }
    __syncthreads();
    if (t < 2) {
        float o = bnode[t];
        for (int p = 0; p < NP; p++) o += pv[p] * Wnode[p * 2 + t];
        out[b * 2 + t] = o;
    }
}

// ===========================================================================
extern "C" void kernel_launch(void* const* d_in, const int* in_sizes, int n_in,
                              void* d_out, int out_size)
{
    const float* feat  = (const float*)d_in[0];
    const float* Wll   = (const float*)d_in[1];
    const float* bll   = (const float*)d_in[2];
    const float* bn1g  = (const float*)d_in[3];
    const float* bn1b  = (const float*)d_in[4];
    const float* bn1m  = (const float*)d_in[5];
    const float* bn1v  = (const float*)d_in[6];
    const float* Wap   = (const float*)d_in[7];
    const float* bap   = (const float*)d_in[8];
    const float* attw  = (const float*)d_in[9];
    const float* Wpa   = (const float*)d_in[10];
    const float* bpa   = (const float*)d_in[11];
    const float* Wpn   = (const float*)d_in[12];
    const float* bpn   = (const float*)d_in[13];
    const float* bn2g  = (const float*)d_in[14];
    const float* bn2b  = (const float*)d_in[15];
    const float* bn2m  = (const float*)d_in[16];
    const float* bn2v  = (const float*)d_in[17];
    const float* Wpool = (const float*)d_in[18];
    const float* bpool = (const float*)d_in[19];
    const float* Wproj = (const float*)d_in[20];
    const float* bproj = (const float*)d_in[21];
    const float* Wnode = (const float*)d_in[22];
    const float* bnode = (const float*)d_in[23];

    cudaFuncSetAttribute(k1, cudaFuncAttributeMaxDynamicSharedMemorySize, K1_SMEM);
    cudaFuncSetAttribute(ky, cudaFuncAttributeMaxDynamicSharedMemorySize, KY_SMEM);
    cudaFuncSetAttribute(k2, cudaFuncAttributeMaxDynamicSharedMemorySize, K2_SMEM);

    k0 <<<(K0_R5 + 255) / 256, 256>>>(Wll, Wap, bll, bn1g, bn1b, bn1m, bn1v,
                                      Wpa, Wpn);
    k1 <<<(MTOT + 125) / 126, 512, K1_SMEM>>>(feat);
    ky <<<NODES / 128, 512, KY_SMEM>>>();
    k2 <<<dim3(6, BS), 256, K2_SMEM>>>(bap, attw);
    k2c<<<BS, 256>>>(bpa, bpn, bn2g, bn2b, bn2m, bn2v, Wpool, bpool,
                     Wproj, bproj, Wnode, bnode, (float*)d_out);
}

// round 16
// speedup vs baseline: 1.1240x; 1.0184x over previous
#include <cuda_runtime.h>
#include <cuda_bf16.h>
#include <math.h>
#include <stdint.h>

#define BS   256
#define SEQ  201
#define DSSL 1024
#define D1   128
#define D2   64
#define NN   67
#define NP   53
#define NPAIR (NN*NN)      // 4489
#define NU   2278          // upper-triangle pairs (i<=j)
#define NUT  2304
#define EPSBN 1e-5f
#define MTOT  (BS*SEQ)     // 51456
#define NODES (BS*NN)      // 17152 = 134*128
#define KYBLK (NODES/128)  // 134

// ---------------- scratch (device globals; no runtime allocation) ----------
__device__ float g_x [NODES * D1];
__device__ float g_y [NODES * D2];         // X @ W_pa
__device__ float g_z [NODES * D2];         // X @ W_pn
__device__ float g_logit[BS * NPAIR];
__device__ uint32_t g_pair[NUT];           // packed (i<<8)|j upper-tri table
__device__ float g_sc1[D1], g_of1[D1];     // folded bias+BN1 scale/offset
// pre-swizzled (SW64, 64B rows) pre-split bf16 weight images
__device__ __align__(16) unsigned char g_Bll_h[32 * 8192];
__device__ __align__(16) unsigned char g_Bll_l[32 * 8192];
__device__ __align__(16) unsigned char g_Bap_h[4 * 4096];   // k-slot-permuted
__device__ __align__(16) unsigned char g_Bap_l[4 * 4096];
__device__ __align__(16) unsigned char g_Byz_h[4 * 8192];   // [W_pa|W_pn]^T
__device__ __align__(16) unsigned char g_Byz_l[4 * 8192];

// ------------------------------ helpers ------------------------------------
__device__ __forceinline__ float selu_f(float v) {
    const float a = 1.6732632423543772f, s = 1.0507009873554805f;
    return v > 0.f ? s * v : s * a * expm1f(v);
}
__device__ __forceinline__ float tanh_f(float x) {
    float e = __expf(2.0f * x);
    return 1.0f - __fdividef(2.0f, e + 1.0f);
}
__host__ __device__ __forceinline__ uint32_t sw64(uint32_t o) {
    return o ^ ((o >> 3) & 0x30);
}
__device__ __forceinline__ uint32_t smem_u32(const void* p) {
    uint32_t a;
    asm("{ .reg .u64 t; cvta.to.shared.u64 t, %1; cvt.u32.u64 %0, t; }"
        : "=r"(a) : "l"(p));
    return a;
}
__device__ __forceinline__ void split2(float v0, float v1, uint32_t& h, uint32_t& l) {
    __nv_bfloat162 hp, lp;
    hp.x = __float2bfloat16(v0);  hp.y = __float2bfloat16(v1);
    lp.x = __float2bfloat16(v0 - __bfloat162float(hp.x));
    lp.y = __float2bfloat16(v1 - __bfloat162float(hp.y));
    h = *reinterpret_cast<uint32_t*>(&hp);
    l = *reinterpret_cast<uint32_t*>(&lp);
}
__device__ __forceinline__ void mma_bf16(float* c,
    uint32_t a0, uint32_t a1, uint32_t a2, uint32_t a3,
    uint32_t b0, uint32_t b1)
{
    asm volatile(
      "mma.sync.aligned.m16n8k16.row.col.f32.bf16.bf16.f32 "
      "{%0,%1,%2,%3},{%4,%5,%6,%7},{%8,%9},{%0,%1,%2,%3};\n"
      : "+f"(c[0]), "+f"(c[1]), "+f"(c[2]), "+f"(c[3])
      : "r"(a0), "r"(a1), "r"(a2), "r"(a3), "r"(b0), "r"(b1));
}
#define LDSM4(r, a) \
    asm volatile("ldmatrix.sync.aligned.m8n8.x4.shared.b16 {%0,%1,%2,%3}, [%4];" \
        : "=r"((r)[0]), "=r"((r)[1]), "=r"((r)[2]), "=r"((r)[3]) : "r"(a))
#define CPA16(d, s) \
    asm volatile("cp.async.ca.shared.global [%0], [%1], 16;" :: "r"(d), "l"(s))
#define CPCOMMIT() asm volatile("cp.async.commit_group;" ::: "memory")
#define CPWAIT()   asm volatile("cp.async.wait_group 0;" ::: "memory")

// ========= K0: weight prep (split+swizzle), pair table, BN1 fold ===========
#define K0_R1 (D1*DSSL)
#define K0_R2 (K0_R1 + D1*D2)
#define K0_R3 (K0_R2 + NUT)
#define K0_R4 (K0_R3 + D1)
#define K0_R5 (K0_R4 + D1*D1)
__global__ void k0(const float* __restrict__ Wll, const float* __restrict__ Wap,
                   const float* __restrict__ bll, const float* __restrict__ g1,
                   const float* __restrict__ b1,  const float* __restrict__ m1,
                   const float* __restrict__ v1,
                   const float* __restrict__ Wpa, const float* __restrict__ Wpn)
{
    int idx = blockIdx.x * 256 + threadIdx.x;
    if (idx < K0_R1) {
        int n = idx >> 10, k = idx & 1023;
        float v = Wll[(size_t)k * D1 + n];
        __nv_bfloat16 h = __float2bfloat16(v);
        __nv_bfloat16 l = __float2bfloat16(v - __bfloat162float(h));
        uint32_t dst = (k >> 5) * 8192 + sw64(n * 64 + (k & 31) * 2);
        *(__nv_bfloat16*)(g_Bll_h + dst) = h;
        *(__nv_bfloat16*)(g_Bll_l + dst) = l;
    } else if (idx < K0_R2) {
        int r = idx - K0_R1;
        int k = r >> 6, c = r & 63;
        float v = Wap[(size_t)k * D2 + c];
        __nv_bfloat16 h = __float2bfloat16(v);
        __nv_bfloat16 l = __float2bfloat16(v - __bfloat162float(h));
        int kk = k & 15;
        int s = 2 * (kk >> 2) + (kk & 1) + 8 * ((kk >> 1) & 1);
        uint32_t col = (uint32_t)(((k >> 4) & 1) * 16 + s);
        uint32_t dst = (k >> 5) * 4096 + sw64(c * 64 + col * 2);
        *(__nv_bfloat16*)(g_Bap_h + dst) = h;
        *(__nv_bfloat16*)(g_Bap_l + dst) = l;
    } else if (idx < K0_R3) {
        int u = idx - K0_R2;
        if (u < NU) {
            float s = sqrtf((float)((2 * NN + 1) * (2 * NN + 1) - 8 * u));
            int i = (int)(((float)(2 * NN + 1) - s) * 0.5f);
            if (i > NN - 1) i = NN - 1;
            if (i < 0) i = 0;
            while (i > 0 && i * NN - i * (i - 1) / 2 > u) i--;
            while ((i + 1) * NN - (i + 1) * i / 2 <= u) i++;
            int j = i + (u - (i * NN - i * (i - 1) / 2));
            g_pair[u] = (uint32_t)((i << 8) | j);
        } else {
            g_pair[u] = 0xFFFFFFFFu;
        }
    } else if (idx < K0_R4) {
        int c = idx - K0_R3;
        float sc = rsqrtf(v1[c] + EPSBN) * g1[c];
        g_sc1[c] = sc;
        g_of1[c] = (bll[c] - m1[c]) * sc + b1[c];
    } else if (idx < K0_R5) {
        int r = idx - K0_R4;
        int n = r >> 7, k = r & 127;
        float v = (n < 64) ? Wpa[(size_t)k * D2 + n]
                           : Wpn[(size_t)k * D2 + (n - 64)];
        __nv_bfloat16 h = __float2bfloat16(v);
        __nv_bfloat16 l = __float2bfloat16(v - __bfloat162float(h));
        uint32_t dst = (k >> 5) * 8192 + sw64(n * 64 + (k & 31) * 2);
        *(__nv_bfloat16*)(g_Byz_h + dst) = h;
        *(__nv_bfloat16*)(g_Byz_l + dst) = l;
    }
}

// ====== K1: feat @ W_ll (hi/lo bf16 3-mma) + fused maxpool3+BN1+selu =======
// BK=64 per outer iteration as two BK=32 sub-tiles -> 16 syncs instead of 32.
#define K1_SMEM 131072
__global__ __launch_bounds__(512) void k1(const float* __restrict__ feat)
{
    extern __shared__ __align__(1024) unsigned char sm1[];
    uint32_t sb = smem_u32(sm1);
    const int t = threadIdx.x, lane = t & 31, wid = t >> 5;
    const int wm = wid >> 1, wn = wid & 1;
    const int m0 = blockIdx.x * 126;

    float acc[8][4];
#pragma unroll
    for (int nf = 0; nf < 8; nf++)
#pragma unroll
        for (int q = 0; q < 4; q++) acc[nf][q] = 0.f;

    const int ar = t >> 2, ak = (t & 3) * 8;
    const int arow_g = min(m0 + ar, MTOT - 1);
    const float* fp = feat + (size_t)arow_g * DSSL + ak;
    float4 fst[4];

    auto ldgA = [&](int kt2) {
        const float* p = fp + kt2 * 64;
        fst[0] = *(const float4*)p;
        fst[1] = *(const float4*)(p + 4);
        fst[2] = *(const float4*)(p + 32);
        fst[3] = *(const float4*)(p + 36);
    };
    auto stsA = [&](int buf) {
        uint32_t o = sw64(ar * 64 + ak * 2);
#pragma unroll
        for (int s = 0; s < 2; s++) {
            const float* vv = (const float*)(fst + s * 2);
            uint32_t h[4], l[4];
#pragma unroll
            for (int q = 0; q < 4; q++) split2(vv[2 * q], vv[2 * q + 1], h[q], l[q]);
            uint32_t base = (uint32_t)buf * 65536u + (uint32_t)s * 32768u;
            *(uint4*)(sm1 + base + o)        = make_uint4(h[0], h[1], h[2], h[3]);
            *(uint4*)(sm1 + base + 8192 + o) = make_uint4(l[0], l[1], l[2], l[3]);
        }
    };
    auto cpB = [&](int kt2, int buf) {
#pragma unroll
        for (int s = 0; s < 2; s++) {
            uint32_t base = sb + buf * 65536 + s * 32768;
            int kt = kt2 * 2 + s;
            CPA16(base + 16384 + t * 16, g_Bll_h + kt * 8192 + t * 16);
            CPA16(base + 24576 + t * 16, g_Bll_l + kt * 8192 + t * 16);
        }
    };
    auto compute = [&](int buf, int s) {
        uint32_t aH = sb + buf * 65536 + s * 32768, aL = aH + 8192;
        uint32_t bH = aH + 16384, bL = aH + 24576;
#pragma unroll
        for (int kf = 0; kf < 2; kf++) {
            uint32_t ah[4], al[4];
            uint32_t off = sw64((wm * 16 + (lane & 15)) * 64 +
                                kf * 32 + (lane >> 4) * 16);
            LDSM4(ah, aH + off);
            LDSM4(al, aL + off);
#pragma unroll
            for (int nf2 = 0; nf2 < 4; nf2++) {
                uint32_t boff = sw64((wn * 64 + nf2 * 16 + (lane & 7) +
                                      ((lane >> 4) & 1) * 8) * 64 +
                                     kf * 32 + ((lane >> 3) & 1) * 16);
                uint32_t bh[4], bl[4];
                LDSM4(bh, bH + boff);
                LDSM4(bl, bL + boff);
                float* c0 = acc[nf2 * 2];
                float* c1 = acc[nf2 * 2 + 1];
                mma_bf16(c0, ah[0], ah[1], ah[2], ah[3], bh[0], bh[1]);
                mma_bf16(c0, ah[0], ah[1], ah[2], ah[3], bl[0], bl[1]);
                mma_bf16(c0, al[0], al[1], al[2], al[3], bh[0], bh[1]);
                mma_bf16(c1, ah[0], ah[1], ah[2], ah[3], bh[2], bh[3]);
                mma_bf16(c1, ah[0], ah[1], ah[2], ah[3], bl[2], bl[3]);
                mma_bf16(c1, al[0], al[1], al[2], al[3], bh[2], bh[3]);
            }
        }
    };

    ldgA(0); cpB(0, 0); CPCOMMIT();
    stsA(0);
    CPWAIT(); __syncthreads();
    for (int kt2 = 0; kt2 < 16; kt2++) {
        int cur = kt2 & 1;
        if (kt2 < 15) { ldgA(kt2 + 1); cpB(kt2 + 1, cur ^ 1); CPCOMMIT(); }
        compute(cur, 0);
        compute(cur, 1);
        if (kt2 < 15) stsA(cur ^ 1);
        CPWAIT(); __syncthreads();
    }

    float* Cep = (float*)sm1;                       // 128 x 132
    const int g = lane >> 2, tg = lane & 3;
#pragma unroll
    for (int nf = 0; nf < 8; nf++) {
        int row = wm * 16 + g;
        int col = wn * 64 + nf * 8 + tg * 2;
        Cep[row * 132 + col]           = acc[nf][0];
        Cep[row * 132 + col + 1]       = acc[nf][1];
        Cep[(row + 8) * 132 + col]     = acc[nf][2];
        Cep[(row + 8) * 132 + col + 1] = acc[nf][3];
    }
    __syncthreads();
#pragma unroll
    for (int pass = 0; pass < 11; pass++) {
        int e = t + pass * 512;
        if (e < 42 * 128) {
            int nl = e >> 7, c = e & 127;
            const float* rp = Cep + (3 * nl) * 132 + c;
            float v = fmaxf(rp[0], fmaxf(rp[132], rp[264]));
            int node = blockIdx.x * 42 + nl;
            if (node < NODES)
                g_x[(size_t)node * D1 + c] = selu_f(v * g_sc1[c] + g_of1[c]);
        }
    }
}

// ====== KYK2: merged kernel. Blocks 0..133 compute [Y|Z] = X@[Wpa|Wpn]; ====
// ====== blocks 134.. run the pair GEMM (R15 k2, byte-identical math). ======
#define O2_ATT  0
#define O2_BAP  256
#define O2_X    1536
#define O2_WH   37888
#define O2_WL   (O2_WH + 16384)
#define K2_SMEM (O2_WL + 16384)      // 70656
__global__ __launch_bounds__(256, 2) void kyk2(
    const float* __restrict__ bap, const float* __restrict__ attw)
{
    extern __shared__ __align__(1024) unsigned char sm2[];
    uint32_t sb = smem_u32(sm2);
    const int t = threadIdx.x, lane = t & 31, w = t >> 5;
    const int g = lane >> 2, tg = lane & 3;

    if (blockIdx.x < KYBLK) {
        // ---------------- KY path: 256 threads, 8 warps (4m x 2n) ----------
        const int wm = w >> 1, wn = w & 1;
        const int m0 = blockIdx.x * 128;

        float acc[2][8][4];
#pragma unroll
        for (int mf = 0; mf < 2; mf++)
#pragma unroll
            for (int nf = 0; nf < 8; nf++)
#pragma unroll
                for (int q = 0; q < 4; q++) acc[mf][nf][q] = 0.f;

        const int ar = t >> 1, ak = (t & 1) * 16;
        const float* fp = g_x + (size_t)(m0 + ar) * D1 + ak;
        float4 fst[4];

        auto ldgA = [&](int kt) {
            const float* p = fp + kt * 32;
            fst[0] = *(const float4*)p;      fst[1] = *(const float4*)(p + 4);
            fst[2] = *(const float4*)(p + 8); fst[3] = *(const float4*)(p + 12);
        };
        auto stsA = [&](int buf) {
            uint32_t base = (uint32_t)buf * 32768u;
#pragma unroll
            for (int s = 0; s < 2; s++) {
                const float* vv = (const float*)(fst + s * 2);
                uint32_t h[4], l[4];
#pragma unroll
                for (int q = 0; q < 4; q++)
                    split2(vv[2 * q], vv[2 * q + 1], h[q], l[q]);
                uint32_t o = sw64(ar * 64 + ak * 2 + s * 16);
                *(uint4*)(sm2 + base + o)        = make_uint4(h[0], h[1], h[2], h[3]);
                *(uint4*)(sm2 + base + 8192 + o) = make_uint4(l[0], l[1], l[2], l[3]);
            }
        };
        auto cpB = [&](int kt, int buf) {
            uint32_t base = sb + buf * 32768;
            CPA16(base + 16384 + t * 32,      g_Byz_h + kt * 8192 + t * 32);
            CPA16(base + 16384 + t * 32 + 16, g_Byz_h + kt * 8192 + t * 32 + 16);
            CPA16(base + 24576 + t * 32,      g_Byz_l + kt * 8192 + t * 32);
            CPA16(base + 24576 + t * 32 + 16, g_Byz_l + kt * 8192 + t * 32 + 16);
        };
        auto compute = [&](int buf) {
            uint32_t aH = sb + buf * 32768, aL = aH + 8192;
            uint32_t bH = aH + 16384, bL = aH + 24576;
#pragma unroll
            for (int kf = 0; kf < 2; kf++) {
                uint32_t ah[2][4], al[2][4];
#pragma unroll
                for (int mf = 0; mf < 2; mf++) {
                    uint32_t off = sw64((wm * 32 + mf * 16 + (lane & 15)) * 64 +
                                        kf * 32 + (lane >> 4) * 16);
                    LDSM4(ah[mf], aH + off);
                    LDSM4(al[mf], aL + off);
                }
#pragma unroll
                for (int nf2 = 0; nf2 < 4; nf2++) {
                    uint32_t boff = sw64((wn * 64 + nf2 * 16 + (lane & 7) +
                                          ((lane >> 4) & 1) * 8) * 64 +
                                         kf * 32 + ((lane >> 3) & 1) * 16);
                    uint32_t bh[4], bl[4];
                    LDSM4(bh, bH + boff);
                    LDSM4(bl, bL + boff);
#pragma unroll
                    for (int mf = 0; mf < 2; mf++) {
                        float* c0 = acc[mf][nf2 * 2];
                        float* c1 = acc[mf][nf2 * 2 + 1];
                        mma_bf16(c0, ah[mf][0], ah[mf][1], ah[mf][2], ah[mf][3], bh[0], bh[1]);
                        mma_bf16(c0, ah[mf][0], ah[mf][1], ah[mf][2], ah[mf][3], bl[0], bl[1]);
                        mma_bf16(c0, al[mf][0], al[mf][1], al[mf][2], al[mf][3], bh[0], bh[1]);
                        mma_bf16(c1, ah[mf][0], ah[mf][1], ah[mf][2], ah[mf][3], bh[2], bh[3]);
                        mma_bf16(c1, ah[mf][0], ah[mf][1], ah[mf][2], ah[mf][3], bl[2], bl[3]);
                        mma_bf16(c1, al[mf][0], al[mf][1], al[mf][2], al[mf][3], bh[2], bh[3]);
                    }
                }
            }
        };

        ldgA(0); cpB(0, 0); CPCOMMIT();
        stsA(0);
        CPWAIT(); __syncthreads();
        for (int kt = 0; kt < 4; kt++) {
            int cur = kt & 1;
            if (kt < 3) { ldgA(kt + 1); cpB(kt + 1, cur ^ 1); CPCOMMIT(); }
            compute(cur);
            if (kt < 3) stsA(cur ^ 1);
            CPWAIT(); __syncthreads();
        }

        float* dst = wn ? g_z : g_y;
#pragma unroll
        for (int mf = 0; mf < 2; mf++)
#pragma unroll
            for (int nf = 0; nf < 8; nf++) {
                int row = m0 + wm * 32 + mf * 16 + g;
                int col = nf * 8 + tg * 2;
                *(float2*)&dst[(size_t)row * D2 + col] =
                    make_float2(acc[mf][nf][0], acc[mf][nf][1]);
                *(float2*)&dst[(size_t)(row + 8) * D2 + col] =
                    make_float2(acc[mf][nf][2], acc[mf][nf][3]);
            }
        return;
    }

    // ---------------- K2 path (R15 structure, unchanged math) --------------
    const int bid = blockIdx.x - KYBLK;
    const int bx = bid % 6, b = bid / 6;
    float* attS  = (float*)(sm2 + O2_ATT);
    float* bapS  = (float*)(sm2 + O2_BAP);
    float* Xs    = (float*)(sm2 + O2_X);        // 67 x 132

    {
        uint32_t dh = sb + O2_WH + t * 64, dl = sb + O2_WL + t * 64;
        const unsigned char* sh = g_Bap_h + t * 64;
        const unsigned char* sl = g_Bap_l + t * 64;
#pragma unroll
        for (int q = 0; q < 4; q++) {
            CPA16(dh + q * 16, sh + q * 16);
            CPA16(dl + q * 16, sl + q * 16);
        }
        CPCOMMIT();
    }
    if (t < 64) { attS[t] = attw[t]; bapS[t] = bap[t]; }
    {
        const float* xg = g_x + (size_t)b * NN * D1;
        for (int i = t; i < NN * 32; i += 256) {
            int row = i >> 5, c4 = (i & 31) * 4;
            *(float4*)(Xs + row * 132 + c4) = *(const float4*)(xg + row * D1 + c4);
        }
    }
    CPWAIT(); __syncthreads();

    float* lg = g_logit + (size_t)b * NPAIR;

    for (int tt = 0; tt < 3; tt++) {
        const int u0 = (bx * 3 + tt) * 128;
        const int ur0 = u0 + w * 16 + g;
        const int ur1 = ur0 + 8;
        const uint32_t pk0 = g_pair[min(ur0, NU - 1)];
        const uint32_t pk1 = g_pair[min(ur1, NU - 1)];
        const float* xi0 = Xs + (pk0 >> 8) * 132;
        const float* xj0 = Xs + (pk0 & 255) * 132;
        const float* xi1 = Xs + (pk1 >> 8) * 132;
        const float* xj1 = Xs + (pk1 & 255) * 132;

        float acc[8][4];
#pragma unroll
        for (int nf = 0; nf < 8; nf++)
#pragma unroll
            for (int q = 0; q < 4; q++) acc[nf][q] = 0.f;

#pragma unroll
        for (int c16 = 0; c16 < 8; c16++) {
            const int kb = c16 * 16 + 4 * tg;
            float4 vi0 = *(const float4*)(xi0 + kb);
            float4 vj0 = *(const float4*)(xj0 + kb);
            float4 vi1 = *(const float4*)(xi1 + kb);
            float4 vj1 = *(const float4*)(xj1 + kb);
            uint32_t a0h, a0l, a1h, a1l, a2h, a2l, a3h, a3l;
            split2(vi0.x * vj0.x, vi0.y * vj0.y, a0h, a0l);
            split2(vi0.z * vj0.z, vi0.w * vj0.w, a2h, a2l);
            split2(vi1.x * vj1.x, vi1.y * vj1.y, a1h, a1l);
            split2(vi1.z * vj1.z, vi1.w * vj1.w, a3h, a3l);
#pragma unroll
            for (int nf2 = 0; nf2 < 4; nf2++) {
                uint32_t boff = sw64((uint32_t)((nf2 * 16 + (lane & 7) +
                                                 ((lane >> 4) & 1) * 8) * 64 +
                                                (c16 & 1) * 32 + ((lane >> 3) & 1) * 16));
                uint32_t bh[4], bl[4];
                LDSM4(bh, sb + O2_WH + (c16 >> 1) * 4096 + boff);
                LDSM4(bl, sb + O2_WL + (c16 >> 1) * 4096 + boff);
                float* c0 = acc[nf2 * 2];
                float* c1 = acc[nf2 * 2 + 1];
                mma_bf16(c0, a0h, a1h, a2h, a3h, bh[0], bh[1]);
                mma_bf16(c0, a0h, a1h, a2h, a3h, bl[0], bl[1]);
                mma_bf16(c0, a0l, a1l, a2l, a3l, bh[0], bh[1]);
                mma_bf16(c1, a0h, a1h, a2h, a3h, bh[2], bh[3]);
                mma_bf16(c1, a0h, a1h, a2h, a3h, bl[2], bl[3]);
                mma_bf16(c1, a0l, a1l, a2l, a3l, bh[2], bh[3]);
            }
        }

        float p0 = 0.f, p1 = 0.f;
#pragma unroll
        for (int nf = 0; nf < 8; nf++) {
            int col = nf * 8 + tg * 2;
            float w0 = attS[col], w1 = attS[col + 1];
            float q0 = bapS[col], q1 = bapS[col + 1];
            p0 += w0 * tanh_f(acc[nf][0] + q0) + w1 * tanh_f(acc[nf][1] + q1);
            p1 += w0 * tanh_f(acc[nf][2] + q0) + w1 * tanh_f(acc[nf][3] + q1);
        }
        p0 += __shfl_xor_sync(0xffffffffu, p0, 1);
        p0 += __shfl_xor_sync(0xffffffffu, p0, 2);
        p1 += __shfl_xor_sync(0xffffffffu, p1, 1);
        p1 += __shfl_xor_sync(0xffffffffu, p1, 2);
        if (tg == 0) {
            if (ur0 < NU) {
                int i2 = (int)(pk0 >> 8), j2 = (int)(pk0 & 255);
                lg[i2 * NN + j2] = p0;
                lg[j2 * NN + i2] = p0;
            }
            if (ur1 < NU) {
                int i2 = (int)(pk1 >> 8), j2 = (int)(pk1 & 255);
                lg[i2 * NN + j2] = p1;
                lg[j2 * NN + i2] = p1;
            }
        }
    }
}

// ==== K2C: softmax + h=selu(BN2(att@Y+Z+b)) + score + top-k + head =========
__global__ __launch_bounds__(256) void k2c(
    const float* __restrict__ bpa, const float* __restrict__ bpn,
    const float* __restrict__ g2, const float* __restrict__ b2,
    const float* __restrict__ m2, const float* __restrict__ v2,
    const float* __restrict__ Wpool, const float* __restrict__ bpool,
    const float* __restrict__ Wproj, const float* __restrict__ bproj,
    const float* __restrict__ Wnode, const float* __restrict__ bnode,
    float* __restrict__ out)
{
    __shared__ float Ys[NN * 68];
    __shared__ float attS[8][68];
    __shared__ float hS[NN * 64];
    __shared__ float scS[NN];
    __shared__ int   sel[NP];
    __shared__ float pv[NP];
    int b = blockIdx.x, t = threadIdx.x;
    int w = t >> 5, l = t & 31;

    for (int i = t; i < NN * 16; i += 256) {
        int row = i >> 4, q = i & 15;
        *(float4*)(Ys + row * 68 + q * 4) =
            *(const float4*)(g_y + ((size_t)b * NN + row) * D2 + q * 4);
    }
    __syncthreads();

    const int c0 = l, c1 = l + 32;
    const float bb0 = bpa[c0] + bpn[c0], bb1 = bpa[c1] + bpn[c1];
    const float s0 = rsqrtf(v2[c0] + EPSBN) * g2[c0];
    const float s1 = rsqrtf(v2[c1] + EPSBN) * g2[c1];
    const float m0 = m2[c0], m1v = m2[c1];
    const float o0 = b2[c0], o1 = b2[c1];
    const float wp0 = Wpool[c0], wp1 = Wpool[c1];
    const float bp = bpool[0];

    for (int i = w; i < NN; i += 8) {
        const float* lr = g_logit + (size_t)b * NPAIR + i * NN;
        float v0 = lr[l];
        float v1 = lr[l + 32];
        float vv2 = (l < 3) ? lr[l + 64] : -1e30f;
        float mx = fmaxf(v0, fmaxf(v1, vv2));
#pragma unroll
        for (int o = 16; o > 0; o >>= 1) mx = fmaxf(mx, __shfl_xor_sync(0xffffffffu, mx, o));
        float e0 = __expf(v0 - mx);
        float e1 = __expf(v1 - mx);
        float e2 = (l < 3) ? __expf(vv2 - mx) : 0.f;
        float ss = e0 + e1 + e2;
#pragma unroll
        for (int o = 16; o > 0; o >>= 1) ss += __shfl_xor_sync(0xffffffffu, ss, o);
        float inv = 1.f / ss;
        attS[w][l] = e0 * inv;
        attS[w][l + 32] = e1 * inv;
        if (l < 3) attS[w][l + 64] = e2 * inv;
        __syncwarp();

        float a0 = 0.f, a1 = 0.f;
        for (int j = 0; j < NN; j++) {
            float a = attS[w][j];
            a0 += a * Ys[j * 68 + c0];
            a1 += a * Ys[j * 68 + c1];
        }
        size_t zb = ((size_t)b * NN + i) * D2;
        float u0 = a0 + g_z[zb + c0] + bb0;
        float u1 = a1 + g_z[zb + c1] + bb1;
        u0 = selu_f((u0 - m0) * s0 + o0);
        u1 = selu_f((u1 - m1v) * s1 + o1);
        hS[i * 64 + c0] = u0;
        hS[i * 64 + c1] = u1;
        float sp = u0 * wp0 + u1 * wp1;
#pragma unroll
        for (int o = 16; o > 0; o >>= 1) sp += __shfl_xor_sync(0xffffffffu, sp, o);
        if (l == 0) scS[i] = 1.f / (1.f + expf(-(sp + bp)));
        __syncwarp();
    }
    __syncthreads();

    if (t < NN) {
        float st = scS[t]; int rank = 0;
        for (int j = 0; j < NN; j++) {
            float sj = scS[j];
            rank += (sj > st) || (sj == st && j < t);
        }
        if (rank < NP) sel[rank] = t;
    }
    __syncthreads();

    for (int p = w; p < NP; p += 8) {
        int node = sel[p];
        float d = hS[node * 64 + l] * Wproj[l] + hS[node * 64 + 32 + l] * Wproj[l + 32];
#pragma unroll
        for (int o = 16; o > 0; o >>= 1) d += __shfl_xor_sync(0xffffffffu, d, o);
        if (l == 0) pv[p] = scS[node] * d + bproj[0];
    }
    __syncthreads();
    if (t < 2) {
        float o = bnode[t];
        for (int p = 0; p < NP; p++) o += pv[p] * Wnode[p * 2 + t];
        out[b * 2 + t] = o;
    }
}

// ===========================================================================
extern "C" void kernel_launch(void* const* d_in, const int* in_sizes, int n_in,
                              void* d_out, int out_size)
{
    const float* feat  = (const float*)d_in[0];
    const float* Wll   = (const float*)d_in[1];
    const float* bll   = (const float*)d_in[2];
    const float* bn1g  = (const float*)d_in[3];
    const float* bn1b  = (const float*)d_in[4];
    const float* bn1m  = (const float*)d_in[5];
    const float* bn1v  = (const float*)d_in[6];
    const float* Wap   = (const float*)d_in[7];
    const float* bap   = (const float*)d_in[8];
    const float* attw  = (const float*)d_in[9];
    const float* Wpa   = (const float*)d_in[10];
    const float* bpa   = (const float*)d_in[11];
    const float* Wpn   = (const float*)d_in[12];
    const float* bpn   = (const float*)d_in[13];
    const float* bn2g  = (const float*)d_in[14];
    const float* bn2b  = (const float*)d_in[15];
    const float* bn2m  = (const float*)d_in[16];
    const float* bn2v  = (const float*)d_in[17];
    const float* Wpool = (const float*)d_in[18];
    const float* bpool = (const float*)d_in[19];
    const float* Wproj = (const float*)d_in[20];
    const float* bproj = (const float*)d_in[21];
    const float* Wnode = (const float*)d_in[22];
    const float* bnode = (const float*)d_in[23];

    cudaFuncSetAttribute(k1,   cudaFuncAttributeMaxDynamicSharedMemorySize, K1_SMEM);
    cudaFuncSetAttribute(kyk2, cudaFuncAttributeMaxDynamicSharedMemorySize, K2_SMEM);

    k0  <<<(K0_R5 + 255) / 256, 256>>>(Wll, Wap, bll, bn1g, bn1b, bn1m, bn1v,
                                       Wpa, Wpn);
    k1  <<<(MTOT + 125) / 126, 512, K1_SMEM>>>(feat);
    kyk2<<<KYBLK + 6 * BS, 256, K2_SMEM>>>(bap, attw);
    k2c <<<BS, 256>>>(bpa, bpn, bn2g, bn2b, bn2m, bn2v, Wpool, bpool,
                      Wproj, bproj, Wnode, bnode, (float*)d_out);
}

// round 17
// speedup vs baseline: 1.1257x; 1.0015x over previous
#include <cuda_runtime.h>
#include <cuda_bf16.h>
#include <math.h>
#include <stdint.h>

#define BS   256
#define SEQ  201
#define DSSL 1024
#define D1   128
#define D2   64
#define NN   67
#define NP   53
#define NPAIR (NN*NN)      // 4489
#define NU   2278          // upper-triangle pairs (i<=j)
#define NUT  2304
#define EPSBN 1e-5f
#define MTOT  (BS*SEQ)     // 51456
#define NODES (BS*NN)      // 17152 = 134*128
#define KYBLK (NODES/128)  // 134

// ---------------- scratch (device globals; no runtime allocation) ----------
__device__ float g_x [NODES * D1];
__device__ float g_y [NODES * D2];         // X @ W_pa
__device__ float g_z [NODES * D2];         // X @ W_pn
__device__ float g_logit[BS * NPAIR];
__device__ uint32_t g_pair[NUT];           // packed (i<<8)|j upper-tri table
__device__ float g_sc1[D1], g_of1[D1];     // folded bias+BN1 scale/offset
// pre-swizzled (SW64, 64B rows) pre-split bf16 weight images
__device__ __align__(16) unsigned char g_Bll_h[32 * 8192];
__device__ __align__(16) unsigned char g_Bll_l[32 * 8192];
__device__ __align__(16) unsigned char g_Bap_h[4 * 4096];   // k-slot-permuted
__device__ __align__(16) unsigned char g_Bap_l[4 * 4096];
__device__ __align__(16) unsigned char g_Byz_h[4 * 8192];   // [W_pa|W_pn]^T
__device__ __align__(16) unsigned char g_Byz_l[4 * 8192];

// ------------------------------ helpers ------------------------------------
__device__ __forceinline__ float selu_f(float v) {
    const float a = 1.6732632423543772f, s = 1.0507009873554805f;
    return v > 0.f ? s * v : s * a * expm1f(v);
}
__device__ __forceinline__ float tanh_f(float x) {
    float e = __expf(2.0f * x);
    return 1.0f - __fdividef(2.0f, e + 1.0f);
}
__host__ __device__ __forceinline__ uint32_t sw64(uint32_t o) {
    return o ^ ((o >> 3) & 0x30);
}
__device__ __forceinline__ uint32_t smem_u32(const void* p) {
    uint32_t a;
    asm("{ .reg .u64 t; cvta.to.shared.u64 t, %1; cvt.u32.u64 %0, t; }"
        : "=r"(a) : "l"(p));
    return a;
}
__device__ __forceinline__ void split2(float v0, float v1, uint32_t& h, uint32_t& l) {
    __nv_bfloat162 hp, lp;
    hp.x = __float2bfloat16(v0);  hp.y = __float2bfloat16(v1);
    lp.x = __float2bfloat16(v0 - __bfloat162float(hp.x));
    lp.y = __float2bfloat16(v1 - __bfloat162float(hp.y));
    h = *reinterpret_cast<uint32_t*>(&hp);
    l = *reinterpret_cast<uint32_t*>(&lp);
}
__device__ __forceinline__ void mma_bf16(float* c,
    uint32_t a0, uint32_t a1, uint32_t a2, uint32_t a3,
    uint32_t b0, uint32_t b1)
{
    asm volatile(
      "mma.sync.aligned.m16n8k16.row.col.f32.bf16.bf16.f32 "
      "{%0,%1,%2,%3},{%4,%5,%6,%7},{%8,%9},{%0,%1,%2,%3};\n"
      : "+f"(c[0]), "+f"(c[1]), "+f"(c[2]), "+f"(c[3])
      : "r"(a0), "r"(a1), "r"(a2), "r"(a3), "r"(b0), "r"(b1));
}
#define LDSM4(r, a) \
    asm volatile("ldmatrix.sync.aligned.m8n8.x4.shared.b16 {%0,%1,%2,%3}, [%4];" \
        : "=r"((r)[0]), "=r"((r)[1]), "=r"((r)[2]), "=r"((r)[3]) : "r"(a))
#define CPA16(d, s) \
    asm volatile("cp.async.ca.shared.global [%0], [%1], 16;" :: "r"(d), "l"(s))
#define CPCOMMIT() asm volatile("cp.async.commit_group;" ::: "memory")
#define CPWAIT()   asm volatile("cp.async.wait_group 0;" ::: "memory")

// ========= K0: weight prep (split+swizzle), pair table, BN1 fold ===========
#define K0_R1 (D1*DSSL)
#define K0_R2 (K0_R1 + D1*D2)
#define K0_R3 (K0_R2 + NUT)
#define K0_R4 (K0_R3 + D1)
#define K0_R5 (K0_R4 + D1*D1)
__global__ void k0(const float* __restrict__ Wll, const float* __restrict__ Wap,
                   const float* __restrict__ bll, const float* __restrict__ g1,
                   const float* __restrict__ b1,  const float* __restrict__ m1,
                   const float* __restrict__ v1,
                   const float* __restrict__ Wpa, const float* __restrict__ Wpn)
{
    int idx = blockIdx.x * 256 + threadIdx.x;
    if (idx < K0_R1) {
        int n = idx >> 10, k = idx & 1023;
        float v = Wll[(size_t)k * D1 + n];
        __nv_bfloat16 h = __float2bfloat16(v);
        __nv_bfloat16 l = __float2bfloat16(v - __bfloat162float(h));
        uint32_t dst = (k >> 5) * 8192 + sw64(n * 64 + (k & 31) * 2);
        *(__nv_bfloat16*)(g_Bll_h + dst) = h;
        *(__nv_bfloat16*)(g_Bll_l + dst) = l;
    } else if (idx < K0_R2) {
        int r = idx - K0_R1;
        int k = r >> 6, c = r & 63;
        float v = Wap[(size_t)k * D2 + c];
        __nv_bfloat16 h = __float2bfloat16(v);
        __nv_bfloat16 l = __float2bfloat16(v - __bfloat162float(h));
        int kk = k & 15;
        int s = 2 * (kk >> 2) + (kk & 1) + 8 * ((kk >> 1) & 1);
        uint32_t col = (uint32_t)(((k >> 4) & 1) * 16 + s);
        uint32_t dst = (k >> 5) * 4096 + sw64(c * 64 + col * 2);
        *(__nv_bfloat16*)(g_Bap_h + dst) = h;
        *(__nv_bfloat16*)(g_Bap_l + dst) = l;
    } else if (idx < K0_R3) {
        int u = idx - K0_R2;
        if (u < NU) {
            float s = sqrtf((float)((2 * NN + 1) * (2 * NN + 1) - 8 * u));
            int i = (int)(((float)(2 * NN + 1) - s) * 0.5f);
            if (i > NN - 1) i = NN - 1;
            if (i < 0) i = 0;
            while (i > 0 && i * NN - i * (i - 1) / 2 > u) i--;
            while ((i + 1) * NN - (i + 1) * i / 2 <= u) i++;
            int j = i + (u - (i * NN - i * (i - 1) / 2));
            g_pair[u] = (uint32_t)((i << 8) | j);
        } else {
            g_pair[u] = 0xFFFFFFFFu;
        }
    } else if (idx < K0_R4) {
        int c = idx - K0_R3;
        float sc = rsqrtf(v1[c] + EPSBN) * g1[c];
        g_sc1[c] = sc;
        g_of1[c] = (bll[c] - m1[c]) * sc + b1[c];
    } else if (idx < K0_R5) {
        int r = idx - K0_R4;
        int n = r >> 7, k = r & 127;
        float v = (n < 64) ? Wpa[(size_t)k * D2 + n]
                           : Wpn[(size_t)k * D2 + (n - 64)];
        __nv_bfloat16 h = __float2bfloat16(v);
        __nv_bfloat16 l = __float2bfloat16(v - __bfloat162float(h));
        uint32_t dst = (k >> 5) * 8192 + sw64(n * 64 + (k & 31) * 2);
        *(__nv_bfloat16*)(g_Byz_h + dst) = h;
        *(__nv_bfloat16*)(g_Byz_l + dst) = l;
    }
}

// ====== K1: feat @ W_ll (hi/lo bf16 3-mma) + fused maxpool3+BN1+selu =======
#define K1_SMEM 131072
__global__ __launch_bounds__(512) void k1(const float* __restrict__ feat)
{
    extern __shared__ __align__(1024) unsigned char sm1[];
    uint32_t sb = smem_u32(sm1);
    const int t = threadIdx.x, lane = t & 31, wid = t >> 5;
    const int wm = wid >> 1, wn = wid & 1;
    const int m0 = blockIdx.x * 126;

    float acc[8][4];
#pragma unroll
    for (int nf = 0; nf < 8; nf++)
#pragma unroll
        for (int q = 0; q < 4; q++) acc[nf][q] = 0.f;

    const int ar = t >> 2, ak = (t & 3) * 8;
    const int arow_g = min(m0 + ar, MTOT - 1);
    const float* fp = feat + (size_t)arow_g * DSSL + ak;
    float4 fst[4];

    auto ldgA = [&](int kt2) {
        const float* p = fp + kt2 * 64;
        fst[0] = *(const float4*)p;
        fst[1] = *(const float4*)(p + 4);
        fst[2] = *(const float4*)(p + 32);
        fst[3] = *(const float4*)(p + 36);
    };
    auto stsA = [&](int buf) {
        uint32_t o = sw64(ar * 64 + ak * 2);
#pragma unroll
        for (int s = 0; s < 2; s++) {
            const float* vv = (const float*)(fst + s * 2);
            uint32_t h[4], l[4];
#pragma unroll
            for (int q = 0; q < 4; q++) split2(vv[2 * q], vv[2 * q + 1], h[q], l[q]);
            uint32_t base = (uint32_t)buf * 65536u + (uint32_t)s * 32768u;
            *(uint4*)(sm1 + base + o)        = make_uint4(h[0], h[1], h[2], h[3]);
            *(uint4*)(sm1 + base + 8192 + o) = make_uint4(l[0], l[1], l[2], l[3]);
        }
    };
    auto cpB = [&](int kt2, int buf) {
#pragma unroll
        for (int s = 0; s < 2; s++) {
            uint32_t base = sb + buf * 65536 + s * 32768;
            int kt = kt2 * 2 + s;
            CPA16(base + 16384 + t * 16, g_Bll_h + kt * 8192 + t * 16);
            CPA16(base + 24576 + t * 16, g_Bll_l + kt * 8192 + t * 16);
        }
    };
    auto compute = [&](int buf, int s) {
        uint32_t aH = sb + buf * 65536 + s * 32768, aL = aH + 8192;
        uint32_t bH = aH + 16384, bL = aH + 24576;
#pragma unroll
        for (int kf = 0; kf < 2; kf++) {
            uint32_t ah[4], al[4];
            uint32_t off = sw64((wm * 16 + (lane & 15)) * 64 +
                                kf * 32 + (lane >> 4) * 16);
            LDSM4(ah, aH + off);
            LDSM4(al, aL + off);
#pragma unroll
            for (int nf2 = 0; nf2 < 4; nf2++) {
                uint32_t boff = sw64((wn * 64 + nf2 * 16 + (lane & 7) +
                                      ((lane >> 4) & 1) * 8) * 64 +
                                     kf * 32 + ((lane >> 3) & 1) * 16);
                uint32_t bh[4], bl[4];
                LDSM4(bh, bH + boff);
                LDSM4(bl, bL + boff);
                float* c0 = acc[nf2 * 2];
                float* c1 = acc[nf2 * 2 + 1];
                mma_bf16(c0, ah[0], ah[1], ah[2], ah[3], bh[0], bh[1]);
                mma_bf16(c0, ah[0], ah[1], ah[2], ah[3], bl[0], bl[1]);
                mma_bf16(c0, al[0], al[1], al[2], al[3], bh[0], bh[1]);
                mma_bf16(c1, ah[0], ah[1], ah[2], ah[3], bh[2], bh[3]);
                mma_bf16(c1, ah[0], ah[1], ah[2], ah[3], bl[2], bl[3]);
                mma_bf16(c1, al[0], al[1], al[2], al[3], bh[2], bh[3]);
            }
        }
    };

    ldgA(0); cpB(0, 0); CPCOMMIT();
    stsA(0);
    CPWAIT(); __syncthreads();
    for (int kt2 = 0; kt2 < 16; kt2++) {
        int cur = kt2 & 1;
        if (kt2 < 15) { ldgA(kt2 + 1); cpB(kt2 + 1, cur ^ 1); CPCOMMIT(); }
        compute(cur, 0);
        compute(cur, 1);
        if (kt2 < 15) stsA(cur ^ 1);
        CPWAIT(); __syncthreads();
    }

    float* Cep = (float*)sm1;                       // 128 x 132
    const int g = lane >> 2, tg = lane & 3;
#pragma unroll
    for (int nf = 0; nf < 8; nf++) {
        int row = wm * 16 + g;
        int col = wn * 64 + nf * 8 + tg * 2;
        Cep[row * 132 + col]           = acc[nf][0];
        Cep[row * 132 + col + 1]       = acc[nf][1];
        Cep[(row + 8) * 132 + col]     = acc[nf][2];
        Cep[(row + 8) * 132 + col + 1] = acc[nf][3];
    }
    __syncthreads();
#pragma unroll
    for (int pass = 0; pass < 11; pass++) {
        int e = t + pass * 512;
        if (e < 42 * 128) {
            int nl = e >> 7, c = e & 127;
            const float* rp = Cep + (3 * nl) * 132 + c;
            float v = fmaxf(rp[0], fmaxf(rp[132], rp[264]));
            int node = blockIdx.x * 42 + nl;
            if (node < NODES)
                g_x[(size_t)node * D1 + c] = selu_f(v * g_sc1[c] + g_of1[c]);
        }
    }
}

// ====== KYK2: merged kernel. Blocks 0..133 compute [Y|Z] = X@[Wpa|Wpn]; ====
// ====== blocks 134.. run the pair GEMM (byte-identical R15 k2 math). =======
#define O2_ATT  0
#define O2_BAP  256
#define O2_X    1536
#define O2_WH   37888
#define O2_WL   (O2_WH + 16384)
#define K2_SMEM (O2_WL + 16384)      // 70656
__global__ __launch_bounds__(256, 2) void kyk2(
    const float* __restrict__ bap, const float* __restrict__ attw)
{
    extern __shared__ __align__(1024) unsigned char sm2[];
    uint32_t sb = smem_u32(sm2);
    const int t = threadIdx.x, lane = t & 31, w = t >> 5;
    const int g = lane >> 2, tg = lane & 3;

    if (blockIdx.x < KYBLK) {
        // ---------------- KY path: 256 threads, 8 warps (4m x 2n) ----------
        const int wm = w >> 1, wn = w & 1;
        const int m0 = blockIdx.x * 128;

        float acc[2][8][4];
#pragma unroll
        for (int mf = 0; mf < 2; mf++)
#pragma unroll
            for (int nf = 0; nf < 8; nf++)
#pragma unroll
                for (int q = 0; q < 4; q++) acc[mf][nf][q] = 0.f;

        const int ar = t >> 1, ak = (t & 1) * 16;
        const float* fp = g_x + (size_t)(m0 + ar) * D1 + ak;
        float4 fst[4];

        auto ldgA = [&](int kt) {
            const float* p = fp + kt * 32;
            fst[0] = *(const float4*)p;      fst[1] = *(const float4*)(p + 4);
            fst[2] = *(const float4*)(p + 8); fst[3] = *(const float4*)(p + 12);
        };
        auto stsA = [&](int buf) {
            uint32_t base = (uint32_t)buf * 32768u;
#pragma unroll
            for (int s = 0; s < 2; s++) {
                const float* vv = (const float*)(fst + s * 2);
                uint32_t h[4], l[4];
#pragma unroll
                for (int q = 0; q < 4; q++)
                    split2(vv[2 * q], vv[2 * q + 1], h[q], l[q]);
                uint32_t o = sw64(ar * 64 + ak * 2 + s * 16);
                *(uint4*)(sm2 + base + o)        = make_uint4(h[0], h[1], h[2], h[3]);
                *(uint4*)(sm2 + base + 8192 + o) = make_uint4(l[0], l[1], l[2], l[3]);
            }
        };
        auto cpB = [&](int kt, int buf) {
            uint32_t base = sb + buf * 32768;
            CPA16(base + 16384 + t * 32,      g_Byz_h + kt * 8192 + t * 32);
            CPA16(base + 16384 + t * 32 + 16, g_Byz_h + kt * 8192 + t * 32 + 16);
            CPA16(base + 24576 + t * 32,      g_Byz_l + kt * 8192 + t * 32);
            CPA16(base + 24576 + t * 32 + 16, g_Byz_l + kt * 8192 + t * 32 + 16);
        };
        auto compute = [&](int buf) {
            uint32_t aH = sb + buf * 32768, aL = aH + 8192;
            uint32_t bH = aH + 16384, bL = aH + 24576;
#pragma unroll
            for (int kf = 0; kf < 2; kf++) {
                uint32_t ah[2][4], al[2][4];
#pragma unroll
                for (int mf = 0; mf < 2; mf++) {
                    uint32_t off = sw64((wm * 32 + mf * 16 + (lane & 15)) * 64 +
                                        kf * 32 + (lane >> 4) * 16);
                    LDSM4(ah[mf], aH + off);
                    LDSM4(al[mf], aL + off);
                }
#pragma unroll
                for (int nf2 = 0; nf2 < 4; nf2++) {
                    uint32_t boff = sw64((wn * 64 + nf2 * 16 + (lane & 7) +
                                          ((lane >> 4) & 1) * 8) * 64 +
                                         kf * 32 + ((lane >> 3) & 1) * 16);
                    uint32_t bh[4], bl[4];
                    LDSM4(bh, bH + boff);
                    LDSM4(bl, bL + boff);
#pragma unroll
                    for (int mf = 0; mf < 2; mf++) {
                        float* c0 = acc[mf][nf2 * 2];
                        float* c1 = acc[mf][nf2 * 2 + 1];
                        mma_bf16(c0, ah[mf][0], ah[mf][1], ah[mf][2], ah[mf][3], bh[0], bh[1]);
                        mma_bf16(c0, ah[mf][0], ah[mf][1], ah[mf][2], ah[mf][3], bl[0], bl[1]);
                        mma_bf16(c0, al[mf][0], al[mf][1], al[mf][2], al[mf][3], bh[0], bh[1]);
                        mma_bf16(c1, ah[mf][0], ah[mf][1], ah[mf][2], ah[mf][3], bh[2], bh[3]);
                        mma_bf16(c1, ah[mf][0], ah[mf][1], ah[mf][2], ah[mf][3], bl[2], bl[3]);
                        mma_bf16(c1, al[mf][0], al[mf][1], al[mf][2], al[mf][3], bh[2], bh[3]);
                    }
                }
            }
        };

        ldgA(0); cpB(0, 0); CPCOMMIT();
        stsA(0);
        CPWAIT(); __syncthreads();
        for (int kt = 0; kt < 4; kt++) {
            int cur = kt & 1;
            if (kt < 3) { ldgA(kt + 1); cpB(kt + 1, cur ^ 1); CPCOMMIT(); }
            compute(cur);
            if (kt < 3) stsA(cur ^ 1);
            CPWAIT(); __syncthreads();
        }

        float* dst = wn ? g_z : g_y;
#pragma unroll
        for (int mf = 0; mf < 2; mf++)
#pragma unroll
            for (int nf = 0; nf < 8; nf++) {
                int row = m0 + wm * 32 + mf * 16 + g;
                int col = nf * 8 + tg * 2;
                *(float2*)&dst[(size_t)row * D2 + col] =
                    make_float2(acc[mf][nf][0], acc[mf][nf][1]);
                *(float2*)&dst[(size_t)(row + 8) * D2 + col] =
                    make_float2(acc[mf][nf][2], acc[mf][nf][3]);
            }
        return;
    }

    // ---------------- K2 path (unchanged math) -----------------------------
    const int bid = blockIdx.x - KYBLK;
    const int bx = bid % 6, b = bid / 6;
    float* attS  = (float*)(sm2 + O2_ATT);
    float* bapS  = (float*)(sm2 + O2_BAP);
    float* Xs    = (float*)(sm2 + O2_X);        // 67 x 132

    {
        uint32_t dh = sb + O2_WH + t * 64, dl = sb + O2_WL + t * 64;
        const unsigned char* sh = g_Bap_h + t * 64;
        const unsigned char* sl = g_Bap_l + t * 64;
#pragma unroll
        for (int q = 0; q < 4; q++) {
            CPA16(dh + q * 16, sh + q * 16);
            CPA16(dl + q * 16, sl + q * 16);
        }
        CPCOMMIT();
    }
    if (t < 64) { attS[t] = attw[t]; bapS[t] = bap[t]; }
    {
        const float* xg = g_x + (size_t)b * NN * D1;
        for (int i = t; i < NN * 32; i += 256) {
            int row = i >> 5, c4 = (i & 31) * 4;
            *(float4*)(Xs + row * 132 + c4) = *(const float4*)(xg + row * D1 + c4);
        }
    }
    CPWAIT(); __syncthreads();

    float* lg = g_logit + (size_t)b * NPAIR;

    for (int tt = 0; tt < 3; tt++) {
        const int u0 = (bx * 3 + tt) * 128;
        const int ur0 = u0 + w * 16 + g;
        const int ur1 = ur0 + 8;
        const uint32_t pk0 = g_pair[min(ur0, NU - 1)];
        const uint32_t pk1 = g_pair[min(ur1, NU - 1)];
        const float* xi0 = Xs + (pk0 >> 8) * 132;
        const float* xj0 = Xs + (pk0 & 255) * 132;
        const float* xi1 = Xs + (pk1 >> 8) * 132;
        const float* xj1 = Xs + (pk1 & 255) * 132;

        float acc[8][4];
#pragma unroll
        for (int nf = 0; nf < 8; nf++)
#pragma unroll
            for (int q = 0; q < 4; q++) acc[nf][q] = 0.f;

#pragma unroll
        for (int c16 = 0; c16 < 8; c16++) {
            const int kb = c16 * 16 + 4 * tg;
            float4 vi0 = *(const float4*)(xi0 + kb);
            float4 vj0 = *(const float4*)(xj0 + kb);
            float4 vi1 = *(const float4*)(xi1 + kb);
            float4 vj1 = *(const float4*)(xj1 + kb);
            uint32_t a0h, a0l, a1h, a1l, a2h, a2l, a3h, a3l;
            split2(vi0.x * vj0.x, vi0.y * vj0.y, a0h, a0l);
            split2(vi0.z * vj0.z, vi0.w * vj0.w, a2h, a2l);
            split2(vi1.x * vj1.x, vi1.y * vj1.y, a1h, a1l);
            split2(vi1.z * vj1.z, vi1.w * vj1.w, a3h, a3l);
#pragma unroll
            for (int nf2 = 0; nf2 < 4; nf2++) {
                uint32_t boff = sw64((uint32_t)((nf2 * 16 + (lane & 7) +
                                                 ((lane >> 4) & 1) * 8) * 64 +
                                                (c16 & 1) * 32 + ((lane >> 3) & 1) * 16));
                uint32_t bh[4], bl[4];
                LDSM4(bh, sb + O2_WH + (c16 >> 1) * 4096 + boff);
                LDSM4(bl, sb + O2_WL + (c16 >> 1) * 4096 + boff);
                float* c0 = acc[nf2 * 2];
                float* c1 = acc[nf2 * 2 + 1];
                mma_bf16(c0, a0h, a1h, a2h, a3h, bh[0], bh[1]);
                mma_bf16(c0, a0h, a1h, a2h, a3h, bl[0], bl[1]);
                mma_bf16(c0, a0l, a1l, a2l, a3l, bh[0], bh[1]);
                mma_bf16(c1, a0h, a1h, a2h, a3h, bh[2], bh[3]);
                mma_bf16(c1, a0h, a1h, a2h, a3h, bl[2], bl[3]);
                mma_bf16(c1, a0l, a1l, a2l, a3l, bh[2], bh[3]);
            }
        }

        float p0 = 0.f, p1 = 0.f;
#pragma unroll
        for (int nf = 0; nf < 8; nf++) {
            int col = nf * 8 + tg * 2;
            float w0 = attS[col], w1 = attS[col + 1];
            float q0 = bapS[col], q1 = bapS[col + 1];
            p0 += w0 * tanh_f(acc[nf][0] + q0) + w1 * tanh_f(acc[nf][1] + q1);
            p1 += w0 * tanh_f(acc[nf][2] + q0) + w1 * tanh_f(acc[nf][3] + q1);
        }
        p0 += __shfl_xor_sync(0xffffffffu, p0, 1);
        p0 += __shfl_xor_sync(0xffffffffu, p0, 2);
        p1 += __shfl_xor_sync(0xffffffffu, p1, 1);
        p1 += __shfl_xor_sync(0xffffffffu, p1, 2);
        if (tg == 0) {
            if (ur0 < NU) {
                int i2 = (int)(pk0 >> 8), j2 = (int)(pk0 & 255);
                lg[i2 * NN + j2] = p0;
                lg[j2 * NN + i2] = p0;
            }
            if (ur1 < NU) {
                int i2 = (int)(pk1 >> 8), j2 = (int)(pk1 & 255);
                lg[i2 * NN + j2] = p1;
                lg[j2 * NN + i2] = p1;
            }
        }
    }
}

// ==== K2C: softmax + h=selu(BN2(att@Y+Z+b)) + score + top-k + head =========
// 512 threads / 16 warps: 2x latency-hiding over the 8-warp version.
__global__ __launch_bounds__(512) void k2c(
    const float* __restrict__ bpa, const float* __restrict__ bpn,
    const float* __restrict__ g2, const float* __restrict__ b2,
    const float* __restrict__ m2, const float* __restrict__ v2,
    const float* __restrict__ Wpool, const float* __restrict__ bpool,
    const float* __restrict__ Wproj, const float* __restrict__ bproj,
    const float* __restrict__ Wnode, const float* __restrict__ bnode,
    float* __restrict__ out)
{
    __shared__ float Ys[NN * 68];
    __shared__ float attS[16][68];
    __shared__ float hS[NN * 64];
    __shared__ float scS[NN];
    __shared__ int   sel[NP];
    __shared__ float pv[NP];
    int b = blockIdx.x, t = threadIdx.x;
    int w = t >> 5, l = t & 31;

    for (int i = t; i < NN * 16; i += 512) {
        int row = i >> 4, q = i & 15;
        *(float4*)(Ys + row * 68 + q * 4) =
            *(const float4*)(g_y + ((size_t)b * NN + row) * D2 + q * 4);
    }
    __syncthreads();

    const int c0 = l, c1 = l + 32;
    const float bb0 = bpa[c0] + bpn[c0], bb1 = bpa[c1] + bpn[c1];
    const float s0 = rsqrtf(v2[c0] + EPSBN) * g2[c0];
    const float s1 = rsqrtf(v2[c1] + EPSBN) * g2[c1];
    const float m0 = m2[c0], m1v = m2[c1];
    const float o0 = b2[c0], o1 = b2[c1];
    const float wp0 = Wpool[c0], wp1 = Wpool[c1];
    const float bp = bpool[0];

    for (int i = w; i < NN; i += 16) {
        const float* lr = g_logit + (size_t)b * NPAIR + i * NN;
        float v0 = lr[l];
        float v1 = lr[l + 32];
        float vv2 = (l < 3) ? lr[l + 64] : -1e30f;
        float mx = fmaxf(v0, fmaxf(v1, vv2));
#pragma unroll
        for (int o = 16; o > 0; o >>= 1) mx = fmaxf(mx, __shfl_xor_sync(0xffffffffu, mx, o));
        float e0 = __expf(v0 - mx);
        float e1 = __expf(v1 - mx);
        float e2 = (l < 3) ? __expf(vv2 - mx) : 0.f;
        float ss = e0 + e1 + e2;
#pragma unroll
        for (int o = 16; o > 0; o >>= 1) ss += __shfl_xor_sync(0xffffffffu, ss, o);
        float inv = 1.f / ss;
        attS[w][l] = e0 * inv;
        attS[w][l + 32] = e1 * inv;
        if (l < 3) attS[w][l + 64] = e2 * inv;
        __syncwarp();

        float a0 = 0.f, a1 = 0.f;
        for (int j = 0; j < NN; j++) {
            float a = attS[w][j];
            a0 += a * Ys[j * 68 + c0];
            a1 += a * Ys[j * 68 + c1];
        }
        size_t zb = ((size_t)b * NN + i) * D2;
        float u0 = a0 + g_z[zb + c0] + bb0;
        float u1 = a1 + g_z[zb + c1] + bb1;
        u0 = selu_f((u0 - m0) * s0 + o0);
        u1 = selu_f((u1 - m1v) * s1 + o1);
        hS[i * 64 + c0] = u0;
        hS[i * 64 + c1] = u1;
        float sp = u0 * wp0 + u1 * wp1;
#pragma unroll
        for (int o = 16; o > 0; o >>= 1) sp += __shfl_xor_sync(0xffffffffu, sp, o);
        if (l == 0) scS[i] = 1.f / (1.f + expf(-(sp + bp)));
        __syncwarp();
    }
    __syncthreads();

    if (t < NN) {
        float st = scS[t]; int rank = 0;
        for (int j = 0; j < NN; j++) {
            float sj = scS[j];
            rank += (sj > st) || (sj == st && j < t);
        }
        if (rank < NP) sel[rank] = t;
    }
    __syncthreads();

    for (int p = w; p < NP; p += 16) {
        int node = sel[p];
        float d = hS[node * 64 + l] * Wproj[l] + hS[node * 64 + 32 + l] * Wproj[l + 32];
#pragma unroll
        for (int o = 16; o > 0; o >>= 1) d += __shfl_xor_sync(0xffffffffu, d, o);
        if (l == 0) pv[p] = scS[node] * d + bproj[0];
    }
    __syncthreads();
    if (t < 2) {
        float o = bnode[t];
        for (int p = 0; p < NP; p++) o += pv[p] * Wnode[p * 2 + t];
        out[b * 2 + t] = o;
    }
}

// ===========================================================================
extern "C" void kernel_launch(void* const* d_in, const int* in_sizes, int n_in,
                              void* d_out, int out_size)
{
    const float* feat  = (const float*)d_in[0];
    const float* Wll   = (const float*)d_in[1];
    const float* bll   = (const float*)d_in[2];
    const float* bn1g  = (const float*)d_in[3];
    const float* bn1b  = (const float*)d_in[4];
    const float* bn1m  = (const float*)d_in[5];
    const float* bn1v  = (const float*)d_in[6];
    const float* Wap   = (const float*)d_in[7];
    const float* bap   = (const float*)d_in[8];
    const float* attw  = (const float*)d_in[9];
    const float* Wpa   = (const float*)d_in[10];
    const float* bpa   = (const float*)d_in[11];
    const float* Wpn   = (const float*)d_in[12];
    const float* bpn   = (const float*)d_in[13];
    const float* bn2g  = (const float*)d_in[14];
    const float* bn2b  = (const float*)d_in[15];
    const float* bn2m  = (const float*)d_in[16];
    const float* bn2v  = (const float*)d_in[17];
    const float* Wpool = (const float*)d_in[18];
    const float* bpool = (const float*)d_in[19];
    const float* Wproj = (const float*)d_in[20];
    const float* bproj = (const float*)d_in[21];
    const float* Wnode = (const float*)d_in[22];
    const float* bnode = (const float*)d_in[23];

    cudaFuncSetAttribute(k1,   cudaFuncAttributeMaxDynamicSharedMemorySize, K1_SMEM);
    cudaFuncSetAttribute(kyk2, cudaFuncAttributeMaxDynamicSharedMemorySize, K2_SMEM);

    k0  <<<(K0_R5 + 255) / 256, 256>>>(Wll, Wap, bll, bn1g, bn1b, bn1m, bn1v,
                                       Wpa, Wpn);
    k1  <<<(MTOT + 125) / 126, 512, K1_SMEM>>>(feat);
    kyk2<<<KYBLK + 6 * BS, 256, K2_SMEM>>>(bap, attw);
    k2c <<<BS, 512>>>(bpa, bpn, bn2g, bn2b, bn2m, bn2v, Wpool, bpool,
                      Wproj, bproj, Wnode, bnode, (float*)d_out);
}